// round 1
// baseline (speedup 1.0000x reference)
#include <cuda_runtime.h>
#include <math.h>

#define BATCH 32
#define SQ 1024
#define SK 1024
#define DIN 512
#define ATTD 512   // attention size == Dmem == Din == 512

#define TBM 128
#define TBN 128
#define TBK 8

// Scratch (static device globals — no runtime allocation)
__device__ float g_x[(size_t)BATCH * SQ * ATTD];   // relu(inputs @ W_input)   64 MB
__device__ float g_m[(size_t)BATCH * SK * ATTD];   // relu(memory @ W_memory)  64 MB
__device__ float g_s[(size_t)BATCH * SQ * SK];     // logits / softmax probs  128 MB

// ---------------------------------------------------------------------------
// Core 128x128 tile GEMM, K templated, double-buffered smem, 8x8 per thread.
// TB=false: B is row-major [K, N] with leading dim ldb.
// TB=true : B is row-major [N, K] accessed transposed (C = A * B^T).
// Ag must point at A + m0*K ; Bg at (TB ? B + n0*K : B + n0).
// ---------------------------------------------------------------------------
template<int K, bool TB>
__device__ __forceinline__ void gemm_core(const float* __restrict__ Ag,
                                          const float* __restrict__ Bg,
                                          int ldb,
                                          float (&acc)[8][8])
{
    __shared__ float As[2][TBK][TBM];
    __shared__ float Bs[2][TBK][TBN];

    const int tid = threadIdx.x;

    // A tile loaders: 128 rows x 8 k, one float4 per thread
    const int a_row = tid >> 1;
    const int a_k4  = (tid & 1) * 4;
    const float* Aptr = Ag + (size_t)a_row * K + a_k4;

    // B tile loaders
    int b_row = 0, b_k4 = 0, b_k = 0, b_n4 = 0;
    const float* Bptr;
    if (TB) {
        b_row = tid >> 1; b_k4 = (tid & 1) * 4;
        Bptr = Bg + (size_t)b_row * K + b_k4;
    } else {
        b_k = tid >> 5; b_n4 = (tid & 31) * 4;
        Bptr = Bg + (size_t)b_k * ldb + b_n4;
    }

    float4 av = *(const float4*)Aptr;
    float4 bv = *(const float4*)Bptr;

    const int tx = tid & 15;
    const int ty = tid >> 4;

    const int NK = K / TBK;
    #pragma unroll 1
    for (int kt = 0; kt < NK; kt++) {
        const int cur = kt & 1;
        As[cur][a_k4 + 0][a_row] = av.x;
        As[cur][a_k4 + 1][a_row] = av.y;
        As[cur][a_k4 + 2][a_row] = av.z;
        As[cur][a_k4 + 3][a_row] = av.w;
        if (TB) {
            Bs[cur][b_k4 + 0][b_row] = bv.x;
            Bs[cur][b_k4 + 1][b_row] = bv.y;
            Bs[cur][b_k4 + 2][b_row] = bv.z;
            Bs[cur][b_k4 + 3][b_row] = bv.w;
        } else {
            *(float4*)&Bs[cur][b_k][b_n4] = bv;
        }
        __syncthreads();

        if (kt + 1 < NK) {
            av = *(const float4*)(Aptr + (kt + 1) * TBK);
            bv = TB ? *(const float4*)(Bptr + (kt + 1) * TBK)
                    : *(const float4*)(Bptr + (size_t)(kt + 1) * TBK * ldb);
        }

        #pragma unroll
        for (int kk = 0; kk < TBK; kk++) {
            float ra[8], rb[8];
            *(float4*)&ra[0] = *(const float4*)&As[cur][kk][ty * 8];
            *(float4*)&ra[4] = *(const float4*)&As[cur][kk][ty * 8 + 4];
            *(float4*)&rb[0] = *(const float4*)&Bs[cur][kk][tx * 8];
            *(float4*)&rb[4] = *(const float4*)&Bs[cur][kk][tx * 8 + 4];
            #pragma unroll
            for (int i = 0; i < 8; i++)
                #pragma unroll
                for (int j = 0; j < 8; j++)
                    acc[i][j] = fmaf(ra[i], rb[j], acc[i][j]);
        }
        __syncthreads();
    }
}

// ---------------------------------------------------------------------------
// 1) projection + relu:  C = relu(A[M,512] @ W[512,512]); which: 0 -> g_x, 1 -> g_m
// ---------------------------------------------------------------------------
__global__ __launch_bounds__(256)
void proj_kernel(const float* __restrict__ A, const float* __restrict__ W, int which)
{
    const int m0 = blockIdx.y * TBM;
    const int n0 = blockIdx.x * TBN;
    float acc[8][8] = {};
    gemm_core<512, false>(A + (size_t)m0 * 512, W + n0, 512, acc);

    float* __restrict__ C = which ? g_m : g_x;
    const int tid = threadIdx.x;
    const int tx = tid & 15, ty = tid >> 4;
    #pragma unroll
    for (int i = 0; i < 8; i++) {
        const size_t row = m0 + ty * 8 + i;
        #pragma unroll
        for (int j = 0; j < 8; j += 4) {
            float4 v;
            v.x = fmaxf(acc[i][j + 0], 0.f);
            v.y = fmaxf(acc[i][j + 1], 0.f);
            v.z = fmaxf(acc[i][j + 2], 0.f);
            v.w = fmaxf(acc[i][j + 3], 0.f);
            *(float4*)&C[row * 512 + n0 + tx * 8 + j] = v;
        }
    }
}

// ---------------------------------------------------------------------------
// 2) logits: S[b] = scale * x[b] @ m[b]^T, masked
// ---------------------------------------------------------------------------
__global__ __launch_bounds__(256)
void logits_kernel(const int* __restrict__ mask)
{
    const int b  = blockIdx.z;
    const int m0 = blockIdx.y * TBM;
    const int n0 = blockIdx.x * TBN;
    float acc[8][8] = {};
    gemm_core<512, true>(g_x + (size_t)b * SQ * ATTD + (size_t)m0 * ATTD,
                         g_m + (size_t)b * SK * ATTD + (size_t)n0 * ATTD,
                         0, acc);

    const int tid = threadIdx.x;
    const int tx = tid & 15, ty = tid >> 4;
    const float SCALE = 0.044194173824159216f;  // 1/sqrt(512)

    int mk[8];
    #pragma unroll
    for (int j = 0; j < 8; j++) mk[j] = mask[(size_t)b * SK + n0 + tx * 8 + j];

    float* __restrict__ C = g_s + (size_t)b * SQ * SK;
    #pragma unroll
    for (int i = 0; i < 8; i++) {
        const size_t row = m0 + ty * 8 + i;
        #pragma unroll
        for (int j = 0; j < 8; j += 4) {
            float4 v;
            v.x = mk[j + 0] ? acc[i][j + 0] * SCALE : -1e30f;
            v.y = mk[j + 1] ? acc[i][j + 1] * SCALE : -1e30f;
            v.z = mk[j + 2] ? acc[i][j + 2] * SCALE : -1e30f;
            v.w = mk[j + 3] ? acc[i][j + 3] * SCALE : -1e30f;
            *(float4*)&C[row * SK + n0 + tx * 8 + j] = v;
        }
    }
}

// ---------------------------------------------------------------------------
// 3) row softmax over SK=1024, in place on g_s. One block (256 thr) per row.
// ---------------------------------------------------------------------------
__global__ __launch_bounds__(256)
void softmax_kernel()
{
    const size_t row = blockIdx.x;
    float* __restrict__ p = g_s + row * SK;
    const int tid = threadIdx.x;
    const int lane = tid & 31, wid = tid >> 5;

    float4 v = ((float4*)p)[tid];
    float mx = fmaxf(fmaxf(v.x, v.y), fmaxf(v.z, v.w));
    #pragma unroll
    for (int o = 16; o > 0; o >>= 1) mx = fmaxf(mx, __shfl_xor_sync(0xffffffffu, mx, o));

    __shared__ float sm[8];
    __shared__ float ss[8];
    if (lane == 0) sm[wid] = mx;
    __syncthreads();
    float m = sm[0];
    #pragma unroll
    for (int w = 1; w < 8; w++) m = fmaxf(m, sm[w]);

    float e0 = __expf(v.x - m);
    float e1 = __expf(v.y - m);
    float e2 = __expf(v.z - m);
    float e3 = __expf(v.w - m);
    float s = (e0 + e1) + (e2 + e3);
    #pragma unroll
    for (int o = 16; o > 0; o >>= 1) s += __shfl_xor_sync(0xffffffffu, s, o);
    if (lane == 0) ss[wid] = s;
    __syncthreads();
    float tot = 0.f;
    #pragma unroll
    for (int w = 0; w < 8; w++) tot += ss[w];

    const float inv = 1.0f / tot;
    float4 r;
    r.x = e0 * inv; r.y = e1 * inv; r.z = e2 * inv; r.w = e3 * inv;
    ((float4*)p)[tid] = r;
}

// ---------------------------------------------------------------------------
// 4) context: out[b,:, :512] = P[b] @ memory[b]   (out row stride = 1024)
// ---------------------------------------------------------------------------
__global__ __launch_bounds__(256)
void context_kernel(const float* __restrict__ memory, float* __restrict__ out)
{
    const int b  = blockIdx.z;
    const int m0 = blockIdx.y * TBM;
    const int n0 = blockIdx.x * TBN;
    float acc[8][8] = {};
    gemm_core<1024, false>(g_s + (size_t)b * SQ * SK + (size_t)m0 * SK,
                           memory + (size_t)b * SK * 512 + n0,
                           512, acc);

    const int tid = threadIdx.x;
    const int tx = tid & 15, ty = tid >> 4;
    #pragma unroll
    for (int i = 0; i < 8; i++) {
        const size_t row = m0 + ty * 8 + i;
        #pragma unroll
        for (int j = 0; j < 8; j += 4) {
            float4 v;
            v.x = acc[i][j + 0]; v.y = acc[i][j + 1];
            v.z = acc[i][j + 2]; v.w = acc[i][j + 3];
            *(float4*)&out[((size_t)b * SQ + row) * 1024 + n0 + tx * 8 + j] = v;
        }
    }
}

// ---------------------------------------------------------------------------
// 5) concat: out[b, q, 512:1024] = inputs[b, q, :]
// ---------------------------------------------------------------------------
__global__ __launch_bounds__(256)
void concat_kernel(const float* __restrict__ inputs, float* __restrict__ out)
{
    const size_t i = (size_t)blockIdx.x * blockDim.x + threadIdx.x; // float4 index
    const size_t row = i >> 7;        // / 128 float4 per 512-float row
    const size_t c   = i & 127;
    float4 v = ((const float4*)inputs)[i];
    ((float4*)out)[row * 256 + 128 + c] = v;
}

// ---------------------------------------------------------------------------
extern "C" void kernel_launch(void* const* d_in, const int* in_sizes, int n_in,
                              void* d_out, int out_size)
{
    const float* inputs = (const float*)d_in[0];
    const float* memory = (const float*)d_in[1];
    const int*   mask   = (const int*)d_in[2];
    const float* Wi     = (const float*)d_in[3];
    const float* Wm     = (const float*)d_in[4];
    float* out = (float*)d_out;

    dim3 blk(256);

    // projections: M = 32*1024 = 32768 rows
    {
        dim3 g(512 / TBN, (BATCH * SQ) / TBM);
        proj_kernel<<<g, blk>>>(inputs, Wi, 0);
        proj_kernel<<<g, blk>>>(memory, Wm, 1);
    }
    // logits + mask
    {
        dim3 g(SK / TBN, SQ / TBM, BATCH);
        logits_kernel<<<g, blk>>>(mask);
    }
    // softmax
    {
        softmax_kernel<<<BATCH * SQ, blk>>>();
    }
    // context
    {
        dim3 g(512 / TBN, SQ / TBM, BATCH);
        context_kernel<<<g, blk>>>(memory, out);
    }
    // concat copy of inputs
    {
        const size_t n4 = (size_t)BATCH * SQ * 512 / 4;
        concat_kernel<<<(unsigned)(n4 / 256), blk>>>(inputs, out);
    }
}

// round 4
// speedup vs baseline: 2.3297x; 2.3297x over previous
#include <cuda_runtime.h>
#include <cuda_bf16.h>
#include <cstdint>

#define BATCH 32
#define SQ 1024
#define SK 1024
#define ATTD 512
#define SCALE 0.044194173824159216f   // 1/sqrt(512)

typedef __nv_bfloat16 bf16;

// ---------------------------------------------------------------------------
// Scratch (static device globals — no runtime allocation)
// ---------------------------------------------------------------------------
__device__ bf16 g_in_hi [(size_t)BATCH * SQ * ATTD];
__device__ bf16 g_in_lo [(size_t)BATCH * SQ * ATTD];
__device__ bf16 g_mem_hi[(size_t)BATCH * SK * ATTD];
__device__ bf16 g_mem_lo[(size_t)BATCH * SK * ATTD];
__device__ bf16 g_wiT_hi[(size_t)ATTD * ATTD];
__device__ bf16 g_wiT_lo[(size_t)ATTD * ATTD];
__device__ bf16 g_wmT_hi[(size_t)ATTD * ATTD];
__device__ bf16 g_wmT_lo[(size_t)ATTD * ATTD];
__device__ bf16 g_x_hi  [(size_t)BATCH * SQ * ATTD];   // relu(in@Wi)*scale, split
__device__ bf16 g_x_lo  [(size_t)BATCH * SQ * ATTD];
__device__ bf16 g_m_hi  [(size_t)BATCH * SK * ATTD];   // relu(mem@Wm), split
__device__ bf16 g_m_lo  [(size_t)BATCH * SK * ATTD];
__device__ bf16 g_memT_hi[(size_t)BATCH * ATTD * SK];  // memory^T per batch [512,1024]
__device__ bf16 g_memT_lo[(size_t)BATCH * ATTD * SK];
__device__ float g_s    [(size_t)BATCH * SQ * SK];     // logits (fp32)
__device__ bf16 g_p_hi  [(size_t)BATCH * SQ * SK];     // softmax probs, split
__device__ bf16 g_p_lo  [(size_t)BATCH * SQ * SK];

// ---------------------------------------------------------------------------
// PTX helpers (sm_80-baseline: mma.sync / ldmatrix / cp.async)
// ---------------------------------------------------------------------------
__device__ __forceinline__ uint32_t s2u(const void* p) {
    return (uint32_t)__cvta_generic_to_shared(p);
}

__device__ __forceinline__ void cp_async16(uint32_t dst, const void* src) {
    asm volatile("cp.async.cg.shared.global [%0], [%1], 16;" :: "r"(dst), "l"(src));
}
#define CP_COMMIT() asm volatile("cp.async.commit_group;" ::: "memory")
#define CP_WAIT3()  asm volatile("cp.async.wait_group 3;" ::: "memory")

__device__ __forceinline__ void ldsm_x4(uint32_t* r, uint32_t addr) {
    asm volatile("ldmatrix.sync.aligned.m8n8.x4.shared.b16 {%0,%1,%2,%3}, [%4];"
                 : "=r"(r[0]), "=r"(r[1]), "=r"(r[2]), "=r"(r[3]) : "r"(addr));
}
__device__ __forceinline__ void mma16816(float* d, const uint32_t* a, const uint32_t* b) {
    asm volatile(
        "mma.sync.aligned.m16n8k16.row.col.f32.bf16.bf16.f32 "
        "{%0,%1,%2,%3}, {%4,%5,%6,%7}, {%8,%9}, {%0,%1,%2,%3};"
        : "+f"(d[0]), "+f"(d[1]), "+f"(d[2]), "+f"(d[3])
        : "r"(a[0]), "r"(a[1]), "r"(a[2]), "r"(a[3]), "r"(b[0]), "r"(b[1]));
}

// ---------------------------------------------------------------------------
// 3-term bf16 mma.sync GEMM: tile 128x128x32, 8 warps (4m x 2n), 4-stage cp.async.
// A [M,K] K-major hi/lo; B [N,K] K-major hi/lo. C = (Ah+Al)(Bh+Bl)^T (lo*lo dropped)
// EPI: 0 proj-x relu*scale->split, 1 proj-m relu->split, 2 logits mask->f32, 3 context->out
// Smem stage (32KB): [0]Ahi(8K) [8K]Alo [16K]Bhi [24K]Blo ; rows: 64B (32 bf16), swizzled.
// ---------------------------------------------------------------------------
#define STAGES 4
#define STAGE_BYTES 32768
#define DSMEM (STAGES * STAGE_BYTES + 1024)

__device__ __forceinline__ uint32_t sw_off(int row, int kb) {
    return (uint32_t)(row * 64 + ((kb ^ ((row >> 1) & 3)) << 4));
}

template<int K, int EPI>
__global__ void __launch_bounds__(256, 1)
gemm_mma_kernel(const bf16* __restrict__ A_hi, const bf16* __restrict__ A_lo, size_t aBS,
                const bf16* __restrict__ B_hi, const bf16* __restrict__ B_lo, size_t bBS,
                const int* __restrict__ mask,
                float* __restrict__ outf,
                bf16* __restrict__ o_hi, bf16* __restrict__ o_lo)
{
    extern __shared__ char dsm_raw[];
    __shared__ int s_mask[128];

    const int tid  = threadIdx.x;
    const int wid  = tid >> 5;
    const int lane = tid & 31;
    const int n0 = blockIdx.x * 128;
    const int m0 = blockIdx.y * 128;
    const int b  = blockIdx.z;

    const uint32_t smem0 = (s2u(dsm_raw) + 1023u) & ~1023u;

    if (EPI == 2 && tid < 128)
        s_mask[tid] = mask[(size_t)b * SK + n0 + tid];

    const bf16* Ah = A_hi + (size_t)b * aBS + (size_t)m0 * K;
    const bf16* Al = A_lo + (size_t)b * aBS + (size_t)m0 * K;
    const bf16* Bh = B_hi + (size_t)b * bBS + (size_t)n0 * K;
    const bf16* Bl = B_lo + (size_t)b * bBS + (size_t)n0 * K;

    const int NC = K / 32;

    // per-thread load slots: 2 x (row, kb) used for all four sub-arrays
    const int r0_ = tid >> 2,          kb0_ = tid & 3;
    const int r1_ = (tid + 256) >> 2,  kb1_ = (tid + 256) & 3;
    const uint32_t d0 = sw_off(r0_, kb0_);
    const uint32_t d1 = sw_off(r1_, kb1_);
    const size_t so0 = (size_t)r0_ * K + kb0_ * 8;
    const size_t so1 = (size_t)r1_ * K + kb1_ * 8;

    #define ISSUE_STAGE(kt) do {                                     \
        uint32_t sb = smem0 + ((kt) % STAGES) * STAGE_BYTES;         \
        size_t ko = (size_t)(kt) * 32;                               \
        cp_async16(sb + d0,          Ah + so0 + ko);                 \
        cp_async16(sb + d0 + 8192,   Al + so0 + ko);                 \
        cp_async16(sb + d0 + 16384,  Bh + so0 + ko);                 \
        cp_async16(sb + d0 + 24576,  Bl + so0 + ko);                 \
        cp_async16(sb + d1,          Ah + so1 + ko);                 \
        cp_async16(sb + d1 + 8192,   Al + so1 + ko);                 \
        cp_async16(sb + d1 + 16384,  Bh + so1 + ko);                 \
        cp_async16(sb + d1 + 24576,  Bl + so1 + ko);                 \
    } while (0)

    // prologue: stages 0..2
    ISSUE_STAGE(0); CP_COMMIT();
    ISSUE_STAGE(1); CP_COMMIT();
    ISSUE_STAGE(2); CP_COMMIT();

    const int wm = (wid & 3) * 32;
    const int wn = (wid >> 2) * 64;

    float acc[2][8][4];
    #pragma unroll
    for (int i = 0; i < 2; i++)
        #pragma unroll
        for (int j = 0; j < 8; j++)
            #pragma unroll
            for (int q = 0; q < 4; q++) acc[i][j][q] = 0.f;

    // ldmatrix lane addressing (constant per thread)
    const int a_row = wm + (lane & 15);            // + mt*16
    const int a_kb  = lane >> 4;                   // + ks*2
    // B non-trans x4: lanes 0-7 -> (n0-7, k-lo), 8-15 -> (n0-7, k-hi),
    //                 16-23 -> (n8-15, k-lo), 24-31 -> (n8-15, k-hi)
    const int b_row = wn + (lane & 7) + ((lane >> 4) & 1) * 8;   // + g*16
    const int b_kb  = (lane >> 3) & 1;                           // + ks*2

    for (int kt = 0; kt < NC; kt++) {
        if (kt + 3 < NC) ISSUE_STAGE(kt + 3);
        CP_COMMIT();
        CP_WAIT3();
        __syncthreads();

        const uint32_t sb = smem0 + (kt % STAGES) * STAGE_BYTES;

        #pragma unroll
        for (int ks = 0; ks < 2; ks++) {
            uint32_t ahi[2][4], alo[2][4];
            #pragma unroll
            for (int mt = 0; mt < 2; mt++) {
                uint32_t ad = sb + sw_off(a_row + mt * 16, a_kb + ks * 2);
                ldsm_x4(ahi[mt], ad);
                ldsm_x4(alo[mt], ad + 8192);
            }
            #pragma unroll
            for (int g = 0; g < 4; g++) {
                uint32_t bhi[4], blo[4];
                uint32_t bd = sb + 16384 + sw_off(b_row + g * 16, b_kb + ks * 2);
                ldsm_x4(bhi, bd);              // non-trans: rows are n, k contiguous
                ldsm_x4(blo, bd + 8192);
                #pragma unroll
                for (int mt = 0; mt < 2; mt++) {
                    mma16816(acc[mt][2 * g + 0], ahi[mt], bhi + 0);
                    mma16816(acc[mt][2 * g + 0], ahi[mt], blo + 0);
                    mma16816(acc[mt][2 * g + 0], alo[mt], bhi + 0);
                    mma16816(acc[mt][2 * g + 1], ahi[mt], bhi + 2);
                    mma16816(acc[mt][2 * g + 1], ahi[mt], blo + 2);
                    mma16816(acc[mt][2 * g + 1], alo[mt], bhi + 2);
                }
            }
        }
        __syncthreads();
    }
    #undef ISSUE_STAGE

    // ------------------------- epilogue -------------------------
    const int er = lane >> 2;        // row within 8-row group
    const int ec = (lane & 3) * 2;   // col pair within n8 tile

    #pragma unroll
    for (int mt = 0; mt < 2; mt++) {
        #pragma unroll
        for (int nt = 0; nt < 8; nt++) {
            const int rA = m0 + wm + mt * 16 + er;
            const int rB = rA + 8;
            const int cl = wn + nt * 8 + ec;        // local col 0..127
            float v0 = acc[mt][nt][0], v1 = acc[mt][nt][1];
            float v2 = acc[mt][nt][2], v3 = acc[mt][nt][3];

            if (EPI == 0 || EPI == 1) {
                v0 = fmaxf(v0, 0.f); v1 = fmaxf(v1, 0.f);
                v2 = fmaxf(v2, 0.f); v3 = fmaxf(v3, 0.f);
                if (EPI == 0) { v0 *= SCALE; v1 *= SCALE; v2 *= SCALE; v3 *= SCALE; }
                __nv_bfloat162 h0, h1, l0, l1;
                h0.x = __float2bfloat16_rn(v0); h0.y = __float2bfloat16_rn(v1);
                h1.x = __float2bfloat16_rn(v2); h1.y = __float2bfloat16_rn(v3);
                l0.x = __float2bfloat16_rn(v0 - __bfloat162float(h0.x));
                l0.y = __float2bfloat16_rn(v1 - __bfloat162float(h0.y));
                l1.x = __float2bfloat16_rn(v2 - __bfloat162float(h1.x));
                l1.y = __float2bfloat16_rn(v3 - __bfloat162float(h1.y));
                size_t oA = (size_t)rA * ATTD + n0 + cl;
                size_t oB = (size_t)rB * ATTD + n0 + cl;
                *(__nv_bfloat162*)(o_hi + oA) = h0;
                *(__nv_bfloat162*)(o_hi + oB) = h1;
                *(__nv_bfloat162*)(o_lo + oA) = l0;
                *(__nv_bfloat162*)(o_lo + oB) = l1;
            } else if (EPI == 2) {
                const int mk0 = s_mask[cl], mk1 = s_mask[cl + 1];
                float2 w0, w1;
                w0.x = mk0 ? v0 : -1e30f; w0.y = mk1 ? v1 : -1e30f;
                w1.x = mk0 ? v2 : -1e30f; w1.y = mk1 ? v3 : -1e30f;
                size_t base = (size_t)b * SQ * SK;
                *(float2*)(outf + base + (size_t)rA * SK + n0 + cl) = w0;
                *(float2*)(outf + base + (size_t)rB * SK + n0 + cl) = w1;
            } else {  // EPI 3: context -> out[:, :512], row stride 1024
                float2 w0, w1;
                w0.x = v0; w0.y = v1; w1.x = v2; w1.y = v3;
                *(float2*)(outf + ((size_t)b * SQ + rA) * 1024 + n0 + cl) = w0;
                *(float2*)(outf + ((size_t)b * SQ + rB) * 1024 + n0 + cl) = w1;
            }
        }
    }
}

// ---------------------------------------------------------------------------
// fp32 -> bf16 hi/lo split (elementwise, float4-vectorized)
// ---------------------------------------------------------------------------
__global__ __launch_bounds__(256)
void split_kernel(const float* __restrict__ src, bf16* __restrict__ hi, bf16* __restrict__ lo)
{
    size_t i = (size_t)blockIdx.x * 256 + threadIdx.x;
    float4 v = ((const float4*)src)[i];
    __nv_bfloat162 h0, h1, l0, l1;
    h0.x = __float2bfloat16_rn(v.x); h0.y = __float2bfloat16_rn(v.y);
    h1.x = __float2bfloat16_rn(v.z); h1.y = __float2bfloat16_rn(v.w);
    l0.x = __float2bfloat16_rn(v.x - __bfloat162float(h0.x));
    l0.y = __float2bfloat16_rn(v.y - __bfloat162float(h0.y));
    l1.x = __float2bfloat16_rn(v.z - __bfloat162float(h1.x));
    l1.y = __float2bfloat16_rn(v.w - __bfloat162float(h1.y));
    ((__nv_bfloat162*)hi)[i * 2]     = h0;
    ((__nv_bfloat162*)hi)[i * 2 + 1] = h1;
    ((__nv_bfloat162*)lo)[i * 2]     = l0;
    ((__nv_bfloat162*)lo)[i * 2 + 1] = l1;
}

// ---------------------------------------------------------------------------
// transpose + split: src [R,C] row-major -> dst [C,R] bf16 hi/lo (per batch z)
// ---------------------------------------------------------------------------
__global__ __launch_bounds__(256)
void transpose_split_kernel(const float* __restrict__ src,
                            bf16* __restrict__ hi, bf16* __restrict__ lo,
                            int R, int C)
{
    __shared__ float t[32][33];
    const int bx = blockIdx.x * 32;        // over C
    const int by = blockIdx.y * 32;        // over R
    const size_t bo = (size_t)blockIdx.z * R * C;
    src += bo; hi += bo; lo += bo;

    #pragma unroll
    for (int i = threadIdx.y; i < 32; i += 8)
        t[i][threadIdx.x] = src[(size_t)(by + i) * C + bx + threadIdx.x];
    __syncthreads();
    #pragma unroll
    for (int i = threadIdx.y; i < 32; i += 8) {
        float v = t[threadIdx.x][i];
        bf16 h = __float2bfloat16_rn(v);
        size_t o = (size_t)(bx + i) * R + by + threadIdx.x;
        hi[o] = h;
        lo[o] = __float2bfloat16_rn(v - __bfloat162float(h));
    }
}

// ---------------------------------------------------------------------------
// row softmax over SK=1024 on g_s; writes probs as bf16 hi/lo
// ---------------------------------------------------------------------------
__global__ __launch_bounds__(256)
void softmax_kernel()
{
    const size_t row = blockIdx.x;
    const float* p = g_s + row * SK;
    const int tid = threadIdx.x;
    const int lane = tid & 31, wid = tid >> 5;

    float4 v = ((const float4*)p)[tid];
    float mx = fmaxf(fmaxf(v.x, v.y), fmaxf(v.z, v.w));
    #pragma unroll
    for (int o = 16; o > 0; o >>= 1) mx = fmaxf(mx, __shfl_xor_sync(0xffffffffu, mx, o));

    __shared__ float sm[8], ss[8];
    if (lane == 0) sm[wid] = mx;
    __syncthreads();
    float m = sm[0];
    #pragma unroll
    for (int w = 1; w < 8; w++) m = fmaxf(m, sm[w]);

    float e0 = __expf(v.x - m), e1 = __expf(v.y - m);
    float e2 = __expf(v.z - m), e3 = __expf(v.w - m);
    float s = (e0 + e1) + (e2 + e3);
    #pragma unroll
    for (int o = 16; o > 0; o >>= 1) s += __shfl_xor_sync(0xffffffffu, s, o);
    if (lane == 0) ss[wid] = s;
    __syncthreads();
    float tot = 0.f;
    #pragma unroll
    for (int w = 0; w < 8; w++) tot += ss[w];
    const float inv = 1.0f / tot;

    float r0 = e0 * inv, r1 = e1 * inv, r2 = e2 * inv, r3 = e3 * inv;
    __nv_bfloat162 h0, h1, l0, l1;
    h0.x = __float2bfloat16_rn(r0); h0.y = __float2bfloat16_rn(r1);
    h1.x = __float2bfloat16_rn(r2); h1.y = __float2bfloat16_rn(r3);
    l0.x = __float2bfloat16_rn(r0 - __bfloat162float(h0.x));
    l0.y = __float2bfloat16_rn(r1 - __bfloat162float(h0.y));
    l1.x = __float2bfloat16_rn(r2 - __bfloat162float(h1.x));
    l1.y = __float2bfloat16_rn(r3 - __bfloat162float(h1.y));
    __nv_bfloat162* ph = (__nv_bfloat162*)(g_p_hi + row * SK);
    __nv_bfloat162* pl = (__nv_bfloat162*)(g_p_lo + row * SK);
    ph[tid * 2] = h0; ph[tid * 2 + 1] = h1;
    pl[tid * 2] = l0; pl[tid * 2 + 1] = l1;
}

// ---------------------------------------------------------------------------
// concat: out[b, q, 512:1024] = inputs[b, q, :]
// ---------------------------------------------------------------------------
__global__ __launch_bounds__(256)
void concat_kernel(const float* __restrict__ inputs, float* __restrict__ out)
{
    const size_t i = (size_t)blockIdx.x * blockDim.x + threadIdx.x;
    const size_t row = i >> 7;
    const size_t c = i & 127;
    float4 v = ((const float4*)inputs)[i];
    ((float4*)out)[row * 256 + 128 + c] = v;
}

// ---------------------------------------------------------------------------
extern "C" void kernel_launch(void* const* d_in, const int* in_sizes, int n_in,
                              void* d_out, int out_size)
{
    const float* inputs = (const float*)d_in[0];
    const float* memory = (const float*)d_in[1];
    const int*   mask   = (const int*)d_in[2];
    const float* Wi     = (const float*)d_in[3];
    const float* Wm     = (const float*)d_in[4];
    float* out = (float*)d_out;

    cudaFuncSetAttribute(gemm_mma_kernel<512, 0>,  cudaFuncAttributeMaxDynamicSharedMemorySize, DSMEM);
    cudaFuncSetAttribute(gemm_mma_kernel<512, 1>,  cudaFuncAttributeMaxDynamicSharedMemorySize, DSMEM);
    cudaFuncSetAttribute(gemm_mma_kernel<512, 2>,  cudaFuncAttributeMaxDynamicSharedMemorySize, DSMEM);
    cudaFuncSetAttribute(gemm_mma_kernel<1024, 3>, cudaFuncAttributeMaxDynamicSharedMemorySize, DSMEM);

    bf16 *in_hi, *in_lo, *mem_hi, *mem_lo, *wiT_hi, *wiT_lo, *wmT_hi, *wmT_lo;
    bf16 *x_hi, *x_lo, *m_hi, *m_lo, *memT_hi, *memT_lo, *p_hi, *p_lo;
    float* sbuf;
    cudaGetSymbolAddress((void**)&in_hi, g_in_hi);   cudaGetSymbolAddress((void**)&in_lo, g_in_lo);
    cudaGetSymbolAddress((void**)&mem_hi, g_mem_hi); cudaGetSymbolAddress((void**)&mem_lo, g_mem_lo);
    cudaGetSymbolAddress((void**)&wiT_hi, g_wiT_hi); cudaGetSymbolAddress((void**)&wiT_lo, g_wiT_lo);
    cudaGetSymbolAddress((void**)&wmT_hi, g_wmT_hi); cudaGetSymbolAddress((void**)&wmT_lo, g_wmT_lo);
    cudaGetSymbolAddress((void**)&x_hi, g_x_hi);     cudaGetSymbolAddress((void**)&x_lo, g_x_lo);
    cudaGetSymbolAddress((void**)&m_hi, g_m_hi);     cudaGetSymbolAddress((void**)&m_lo, g_m_lo);
    cudaGetSymbolAddress((void**)&memT_hi, g_memT_hi); cudaGetSymbolAddress((void**)&memT_lo, g_memT_lo);
    cudaGetSymbolAddress((void**)&p_hi, g_p_hi);     cudaGetSymbolAddress((void**)&p_lo, g_p_lo);
    cudaGetSymbolAddress((void**)&sbuf, g_s);

    // 1) conversions
    split_kernel<<<16384, 256>>>(inputs, in_hi, in_lo);
    split_kernel<<<16384, 256>>>(memory, mem_hi, mem_lo);
    transpose_split_kernel<<<dim3(16, 16, 1), dim3(32, 8)>>>(Wi, wiT_hi, wiT_lo, 512, 512);
    transpose_split_kernel<<<dim3(16, 16, 1), dim3(32, 8)>>>(Wm, wmT_hi, wmT_lo, 512, 512);
    transpose_split_kernel<<<dim3(16, 32, 32), dim3(32, 8)>>>(memory, memT_hi, memT_lo, 1024, 512);

    // 2) projections (M = 32768, N = 512)
    gemm_mma_kernel<512, 0><<<dim3(4, 256, 1), 256, DSMEM>>>(
        in_hi, in_lo, 0, wiT_hi, wiT_lo, 0, nullptr, nullptr, x_hi, x_lo);
    gemm_mma_kernel<512, 1><<<dim3(4, 256, 1), 256, DSMEM>>>(
        mem_hi, mem_lo, 0, wmT_hi, wmT_lo, 0, nullptr, nullptr, m_hi, m_lo);

    // 3) logits: per batch x @ m^T (scale folded into x), masked -> g_s
    gemm_mma_kernel<512, 2><<<dim3(8, 8, 32), 256, DSMEM>>>(
        x_hi, x_lo, (size_t)SQ * ATTD, m_hi, m_lo, (size_t)SK * ATTD,
        mask, sbuf, nullptr, nullptr);

    // 4) softmax -> p (bf16 hi/lo)
    softmax_kernel<<<BATCH * SQ, 256>>>();

    // 5) context: per batch P @ memory -> out[:, :512]
    gemm_mma_kernel<1024, 3><<<dim3(4, 8, 32), 256, DSMEM>>>(
        p_hi, p_lo, (size_t)SQ * SK, memT_hi, memT_lo, (size_t)ATTD * SK,
        nullptr, out, nullptr, nullptr);

    // 6) concat
    concat_kernel<<<(unsigned)(((size_t)BATCH * SQ * 512 / 4) / 256), 256>>>(inputs, out);
}

// round 5
// speedup vs baseline: 5.6284x; 2.4160x over previous
#include <cuda_runtime.h>
#include <cuda_bf16.h>
#include <cstdint>

#define BATCH 32
#define SQ 1024
#define SK 1024
#define ATTD 512
#define SCALE 0.044194173824159216f   // 1/sqrt(512)

typedef __nv_bfloat16 bf16;

// ---------------------------------------------------------------------------
// Scratch (static device globals — no runtime allocation)
// ---------------------------------------------------------------------------
__device__ bf16 g_in_b [(size_t)BATCH * SQ * ATTD];    // inputs bf16
__device__ bf16 g_mem_b[(size_t)BATCH * SK * ATTD];    // memory bf16
__device__ bf16 g_wiT  [(size_t)ATTD * ATTD];          // Wi^T bf16
__device__ bf16 g_wmT  [(size_t)ATTD * ATTD];          // Wm^T bf16
__device__ bf16 g_x    [(size_t)BATCH * SQ * ATTD];    // relu(in@Wi)*scale
__device__ bf16 g_m    [(size_t)BATCH * SK * ATTD];    // relu(mem@Wm)
__device__ bf16 g_memT [(size_t)BATCH * ATTD * SK];    // memory^T per batch
__device__ float g_s   [(size_t)BATCH * SQ * SK];      // logits fp32
__device__ bf16 g_p    [(size_t)BATCH * SQ * SK];      // softmax probs bf16

// ---------------------------------------------------------------------------
// PTX helpers
// ---------------------------------------------------------------------------
__device__ __forceinline__ uint32_t s2u(const void* p) {
    return (uint32_t)__cvta_generic_to_shared(p);
}
__device__ __forceinline__ void cp_async16(uint32_t dst, const void* src) {
    asm volatile("cp.async.cg.shared.global [%0], [%1], 16;" :: "r"(dst), "l"(src));
}
#define CP_COMMIT() asm volatile("cp.async.commit_group;" ::: "memory")
#define CP_WAIT3()  asm volatile("cp.async.wait_group 3;" ::: "memory")

__device__ __forceinline__ void ldsm_x4(uint32_t* r, uint32_t addr) {
    asm volatile("ldmatrix.sync.aligned.m8n8.x4.shared.b16 {%0,%1,%2,%3}, [%4];"
                 : "=r"(r[0]), "=r"(r[1]), "=r"(r[2]), "=r"(r[3]) : "r"(addr));
}
__device__ __forceinline__ void mma16816(float* d, const uint32_t* a, const uint32_t* b) {
    asm volatile(
        "mma.sync.aligned.m16n8k16.row.col.f32.bf16.bf16.f32 "
        "{%0,%1,%2,%3}, {%4,%5,%6,%7}, {%8,%9}, {%0,%1,%2,%3};"
        : "+f"(d[0]), "+f"(d[1]), "+f"(d[2]), "+f"(d[3])
        : "r"(a[0]), "r"(a[1]), "r"(a[2]), "r"(a[3]), "r"(b[0]), "r"(b[1]));
}

// ---------------------------------------------------------------------------
// bf16 mma.sync GEMM: tile 128x128x32, 8 warps (4m x 2n), 4-stage cp.async.
// A [M,K] K-major bf16; B [N,K] K-major bf16. C = A B^T.
// EPI: 0 proj-x relu*scale->bf16, 1 proj-m relu->bf16, 2 logits mask->f32, 3 context->out
// Stage (16KB): [0]A(8K) [8K]B(8K); rows 64B (32 bf16), XOR-swizzled.
// ---------------------------------------------------------------------------
#define STAGES 4
#define STAGE_BYTES 16384
#define DSMEM (STAGES * STAGE_BYTES + 1024)

__device__ __forceinline__ uint32_t sw_off(int row, int kb) {
    return (uint32_t)(row * 64 + ((kb ^ ((row >> 1) & 3)) << 4));
}

template<int K, int EPI>
__global__ void __launch_bounds__(256, 2)
gemm_mma_kernel(const bf16* __restrict__ A, size_t aBS,
                const bf16* __restrict__ B, size_t bBS,
                const int* __restrict__ mask,
                float* __restrict__ outf,
                bf16* __restrict__ obf)
{
    extern __shared__ char dsm_raw[];
    __shared__ int s_mask[128];

    const int tid  = threadIdx.x;
    const int wid  = tid >> 5;
    const int lane = tid & 31;
    const int n0 = blockIdx.x * 128;
    const int m0 = blockIdx.y * 128;
    const int b  = blockIdx.z;

    const uint32_t smem0 = (s2u(dsm_raw) + 1023u) & ~1023u;

    if (EPI == 2 && tid < 128)
        s_mask[tid] = mask[(size_t)b * SK + n0 + tid];

    const bf16* Ag = A + (size_t)b * aBS + (size_t)m0 * K;
    const bf16* Bg = B + (size_t)b * bBS + (size_t)n0 * K;

    const int NC = K / 32;

    // per-thread load slots: 2 x (row, kb)
    const int r0_ = tid >> 2,          kb0_ = tid & 3;
    const int r1_ = (tid + 256) >> 2,  kb1_ = (tid + 256) & 3;
    const uint32_t d0 = sw_off(r0_, kb0_);
    const uint32_t d1 = sw_off(r1_, kb1_);
    const size_t so0 = (size_t)r0_ * K + kb0_ * 8;
    const size_t so1 = (size_t)r1_ * K + kb1_ * 8;

    #define ISSUE_STAGE(kt) do {                                     \
        uint32_t sb = smem0 + ((kt) % STAGES) * STAGE_BYTES;         \
        size_t ko = (size_t)(kt) * 32;                               \
        cp_async16(sb + d0,         Ag + so0 + ko);                  \
        cp_async16(sb + d1,         Ag + so1 + ko);                  \
        cp_async16(sb + d0 + 8192,  Bg + so0 + ko);                  \
        cp_async16(sb + d1 + 8192,  Bg + so1 + ko);                  \
    } while (0)

    ISSUE_STAGE(0); CP_COMMIT();
    ISSUE_STAGE(1); CP_COMMIT();
    ISSUE_STAGE(2); CP_COMMIT();

    const int wm = (wid & 3) * 32;
    const int wn = (wid >> 2) * 64;

    float acc[2][8][4];
    #pragma unroll
    for (int i = 0; i < 2; i++)
        #pragma unroll
        for (int j = 0; j < 8; j++)
            #pragma unroll
            for (int q = 0; q < 4; q++) acc[i][j][q] = 0.f;

    const int a_row = wm + (lane & 15);
    const int a_kb  = lane >> 4;
    const int b_row = wn + (lane & 7) + ((lane >> 4) & 1) * 8;
    const int b_kb  = (lane >> 3) & 1;

    for (int kt = 0; kt < NC; kt++) {
        if (kt + 3 < NC) ISSUE_STAGE(kt + 3);
        CP_COMMIT();
        CP_WAIT3();
        __syncthreads();

        const uint32_t sb = smem0 + (kt % STAGES) * STAGE_BYTES;

        #pragma unroll
        for (int ks = 0; ks < 2; ks++) {
            uint32_t af[2][4];
            #pragma unroll
            for (int mt = 0; mt < 2; mt++)
                ldsm_x4(af[mt], sb + sw_off(a_row + mt * 16, a_kb + ks * 2));
            #pragma unroll
            for (int g = 0; g < 4; g++) {
                uint32_t bfog[4];
                ldsm_x4(bfog, sb + 8192 + sw_off(b_row + g * 16, b_kb + ks * 2));
                #pragma unroll
                for (int mt = 0; mt < 2; mt++) {
                    mma16816(acc[mt][2 * g + 0], af[mt], bfog + 0);
                    mma16816(acc[mt][2 * g + 1], af[mt], bfog + 2);
                }
            }
        }
        __syncthreads();
    }
    #undef ISSUE_STAGE

    // ------------------------- epilogue -------------------------
    const int er = lane >> 2;
    const int ec = (lane & 3) * 2;

    #pragma unroll
    for (int mt = 0; mt < 2; mt++) {
        #pragma unroll
        for (int nt = 0; nt < 8; nt++) {
            const int rA = m0 + wm + mt * 16 + er;
            const int rB = rA + 8;
            const int cl = wn + nt * 8 + ec;
            float v0 = acc[mt][nt][0], v1 = acc[mt][nt][1];
            float v2 = acc[mt][nt][2], v3 = acc[mt][nt][3];

            if (EPI == 0 || EPI == 1) {
                v0 = fmaxf(v0, 0.f); v1 = fmaxf(v1, 0.f);
                v2 = fmaxf(v2, 0.f); v3 = fmaxf(v3, 0.f);
                if (EPI == 0) { v0 *= SCALE; v1 *= SCALE; v2 *= SCALE; v3 *= SCALE; }
                __nv_bfloat162 h0, h1;
                h0.x = __float2bfloat16_rn(v0); h0.y = __float2bfloat16_rn(v1);
                h1.x = __float2bfloat16_rn(v2); h1.y = __float2bfloat16_rn(v3);
                *(__nv_bfloat162*)(obf + (size_t)rA * ATTD + n0 + cl) = h0;
                *(__nv_bfloat162*)(obf + (size_t)rB * ATTD + n0 + cl) = h1;
            } else if (EPI == 2) {
                const int mk0 = s_mask[cl], mk1 = s_mask[cl + 1];
                float2 w0, w1;
                w0.x = mk0 ? v0 : -1e30f; w0.y = mk1 ? v1 : -1e30f;
                w1.x = mk0 ? v2 : -1e30f; w1.y = mk1 ? v3 : -1e30f;
                size_t base = (size_t)b * SQ * SK;
                *(float2*)(outf + base + (size_t)rA * SK + n0 + cl) = w0;
                *(float2*)(outf + base + (size_t)rB * SK + n0 + cl) = w1;
            } else {  // EPI 3: context -> out[:, :512], row stride 1024
                float2 w0, w1;
                w0.x = v0; w0.y = v1; w1.x = v2; w1.y = v3;
                *(float2*)(outf + ((size_t)b * SQ + rA) * 1024 + n0 + cl) = w0;
                *(float2*)(outf + ((size_t)b * SQ + rB) * 1024 + n0 + cl) = w1;
            }
        }
    }
}

// ---------------------------------------------------------------------------
// inputs: fp32 -> bf16, fused with concat copy to out[:, 512:]
// ---------------------------------------------------------------------------
__global__ __launch_bounds__(256)
void conv_inputs_kernel(const float* __restrict__ src, bf16* __restrict__ dst,
                        float* __restrict__ out)
{
    const size_t i = (size_t)blockIdx.x * 256 + threadIdx.x;   // float4 index
    const size_t row = i >> 7;
    const size_t c = i & 127;
    float4 v = ((const float4*)src)[i];
    ((float4*)out)[row * 256 + 128 + c] = v;   // concat half
    __nv_bfloat162 h0, h1;
    h0.x = __float2bfloat16_rn(v.x); h0.y = __float2bfloat16_rn(v.y);
    h1.x = __float2bfloat16_rn(v.z); h1.y = __float2bfloat16_rn(v.w);
    ((__nv_bfloat162*)dst)[i * 2]     = h0;
    ((__nv_bfloat162*)dst)[i * 2 + 1] = h1;
}

// ---------------------------------------------------------------------------
// memory: fp32 [1024,512] per batch -> bf16 row-major AND bf16 transposed [512,1024]
// ---------------------------------------------------------------------------
__global__ __launch_bounds__(256)
void conv_memory_kernel(const float* __restrict__ src,
                        bf16* __restrict__ mem_b, bf16* __restrict__ memT)
{
    __shared__ float t[32][33];
    const int bx = blockIdx.x * 32;   // over C=512
    const int by = blockIdx.y * 32;   // over R=1024
    const size_t bo = (size_t)blockIdx.z * SK * ATTD;
    src += bo; mem_b += bo; memT += bo;

    #pragma unroll
    for (int i = threadIdx.y; i < 32; i += 8) {
        float v = src[(size_t)(by + i) * ATTD + bx + threadIdx.x];
        t[i][threadIdx.x] = v;
        mem_b[(size_t)(by + i) * ATTD + bx + threadIdx.x] = __float2bfloat16_rn(v);
    }
    __syncthreads();
    #pragma unroll
    for (int i = threadIdx.y; i < 32; i += 8)
        memT[(size_t)(bx + i) * SK + by + threadIdx.x] =
            __float2bfloat16_rn(t[threadIdx.x][i]);
}

// ---------------------------------------------------------------------------
// W [512,512] fp32 -> W^T bf16
// ---------------------------------------------------------------------------
__global__ __launch_bounds__(256)
void convW_kernel(const float* __restrict__ src, bf16* __restrict__ dstT)
{
    __shared__ float t[32][33];
    const int bx = blockIdx.x * 32;
    const int by = blockIdx.y * 32;
    #pragma unroll
    for (int i = threadIdx.y; i < 32; i += 8)
        t[i][threadIdx.x] = src[(size_t)(by + i) * ATTD + bx + threadIdx.x];
    __syncthreads();
    #pragma unroll
    for (int i = threadIdx.y; i < 32; i += 8)
        dstT[(size_t)(bx + i) * ATTD + by + threadIdx.x] =
            __float2bfloat16_rn(t[threadIdx.x][i]);
}

// ---------------------------------------------------------------------------
// row softmax over SK=1024 on g_s; writes probs bf16
// ---------------------------------------------------------------------------
__global__ __launch_bounds__(256)
void softmax_kernel()
{
    const size_t row = blockIdx.x;
    const float* p = g_s + row * SK;
    const int tid = threadIdx.x;
    const int lane = tid & 31, wid = tid >> 5;

    float4 v = ((const float4*)p)[tid];
    float mx = fmaxf(fmaxf(v.x, v.y), fmaxf(v.z, v.w));
    #pragma unroll
    for (int o = 16; o > 0; o >>= 1) mx = fmaxf(mx, __shfl_xor_sync(0xffffffffu, mx, o));

    __shared__ float sm[8], ss[8];
    if (lane == 0) sm[wid] = mx;
    __syncthreads();
    float m = sm[0];
    #pragma unroll
    for (int w = 1; w < 8; w++) m = fmaxf(m, sm[w]);

    float e0 = __expf(v.x - m), e1 = __expf(v.y - m);
    float e2 = __expf(v.z - m), e3 = __expf(v.w - m);
    float s = (e0 + e1) + (e2 + e3);
    #pragma unroll
    for (int o = 16; o > 0; o >>= 1) s += __shfl_xor_sync(0xffffffffu, s, o);
    if (lane == 0) ss[wid] = s;
    __syncthreads();
    float tot = 0.f;
    #pragma unroll
    for (int w = 0; w < 8; w++) tot += ss[w];
    const float inv = 1.0f / tot;

    __nv_bfloat162 h0, h1;
    h0.x = __float2bfloat16_rn(e0 * inv); h0.y = __float2bfloat16_rn(e1 * inv);
    h1.x = __float2bfloat16_rn(e2 * inv); h1.y = __float2bfloat16_rn(e3 * inv);
    __nv_bfloat162* ph = (__nv_bfloat162*)(g_p + row * SK);
    ph[tid * 2] = h0; ph[tid * 2 + 1] = h1;
}

// ---------------------------------------------------------------------------
extern "C" void kernel_launch(void* const* d_in, const int* in_sizes, int n_in,
                              void* d_out, int out_size)
{
    const float* inputs = (const float*)d_in[0];
    const float* memory = (const float*)d_in[1];
    const int*   mask   = (const int*)d_in[2];
    const float* Wi     = (const float*)d_in[3];
    const float* Wm     = (const float*)d_in[4];
    float* out = (float*)d_out;

    cudaFuncSetAttribute(gemm_mma_kernel<512, 0>,  cudaFuncAttributeMaxDynamicSharedMemorySize, DSMEM);
    cudaFuncSetAttribute(gemm_mma_kernel<512, 1>,  cudaFuncAttributeMaxDynamicSharedMemorySize, DSMEM);
    cudaFuncSetAttribute(gemm_mma_kernel<512, 2>,  cudaFuncAttributeMaxDynamicSharedMemorySize, DSMEM);
    cudaFuncSetAttribute(gemm_mma_kernel<1024, 3>, cudaFuncAttributeMaxDynamicSharedMemorySize, DSMEM);

    bf16 *in_b, *mem_b, *wiT, *wmT, *x_b, *m_b, *memT, *p_b;
    float* sbuf;
    cudaGetSymbolAddress((void**)&in_b, g_in_b);
    cudaGetSymbolAddress((void**)&mem_b, g_mem_b);
    cudaGetSymbolAddress((void**)&wiT, g_wiT);
    cudaGetSymbolAddress((void**)&wmT, g_wmT);
    cudaGetSymbolAddress((void**)&x_b, g_x);
    cudaGetSymbolAddress((void**)&m_b, g_m);
    cudaGetSymbolAddress((void**)&memT, g_memT);
    cudaGetSymbolAddress((void**)&p_b, g_p);
    cudaGetSymbolAddress((void**)&sbuf, g_s);

    // 1) conversions (concat fused into inputs convert)
    conv_inputs_kernel<<<16384, 256>>>(inputs, in_b, out);
    conv_memory_kernel<<<dim3(16, 32, 32), dim3(32, 8)>>>(memory, mem_b, memT);
    convW_kernel<<<dim3(16, 16), dim3(32, 8)>>>(Wi, wiT);
    convW_kernel<<<dim3(16, 16), dim3(32, 8)>>>(Wm, wmT);

    // 2) projections (M = 32768, N = 512)
    gemm_mma_kernel<512, 0><<<dim3(4, 256, 1), 256, DSMEM>>>(
        in_b, 0, wiT, 0, nullptr, nullptr, x_b);
    gemm_mma_kernel<512, 1><<<dim3(4, 256, 1), 256, DSMEM>>>(
        mem_b, 0, wmT, 0, nullptr, nullptr, m_b);

    // 3) logits: per batch x @ m^T (scale folded into x), masked -> g_s
    gemm_mma_kernel<512, 2><<<dim3(8, 8, 32), 256, DSMEM>>>(
        x_b, (size_t)SQ * ATTD, m_b, (size_t)SK * ATTD, mask, sbuf, nullptr);

    // 4) softmax -> p bf16
    softmax_kernel<<<BATCH * SQ, 256>>>();

    // 5) context: per batch P @ memory -> out[:, :512]
    gemm_mma_kernel<1024, 3><<<dim3(4, 8, 32), 256, DSMEM>>>(
        p_b, (size_t)SQ * SK, memT, (size_t)ATTD * SK, nullptr, out, nullptr);
}

// round 6
// speedup vs baseline: 6.1887x; 1.0996x over previous
#include <cuda_runtime.h>
#include <cuda_bf16.h>
#include <cuda_fp16.h>
#include <cstdint>

#define BATCH 32
#define SQ 1024
#define SK 1024
#define ATTD 512
#define SCALE 0.044194173824159216f   // 1/sqrt(512)
#define MASKED_LOGIT -60000.0f        // finite in fp16; exp -> 0

typedef __nv_bfloat16 bf16;

// ---------------------------------------------------------------------------
// Scratch (static device globals — no runtime allocation)
// ---------------------------------------------------------------------------
__device__ bf16 g_in_b [(size_t)BATCH * SQ * ATTD];    // inputs bf16
__device__ bf16 g_mem_b[(size_t)BATCH * SK * ATTD];    // memory bf16
__device__ bf16 g_wiT  [(size_t)ATTD * ATTD];          // Wi^T bf16
__device__ bf16 g_wmT  [(size_t)ATTD * ATTD];          // Wm^T bf16
__device__ bf16 g_x    [(size_t)BATCH * SQ * ATTD];    // relu(in@Wi)*scale
__device__ bf16 g_m    [(size_t)BATCH * SK * ATTD];    // relu(mem@Wm)
__device__ bf16 g_memT [(size_t)BATCH * ATTD * SK];    // memory^T per batch
__device__ __half g_sh [(size_t)BATCH * SQ * SK];      // logits fp16 (masked)
__device__ bf16 g_p    [(size_t)BATCH * SQ * SK];      // softmax probs bf16

// ---------------------------------------------------------------------------
// PTX helpers
// ---------------------------------------------------------------------------
__device__ __forceinline__ uint32_t s2u(const void* p) {
    return (uint32_t)__cvta_generic_to_shared(p);
}
__device__ __forceinline__ void cp_async16(uint32_t dst, const void* src) {
    asm volatile("cp.async.cg.shared.global [%0], [%1], 16;" :: "r"(dst), "l"(src));
}
#define CP_COMMIT() asm volatile("cp.async.commit_group;" ::: "memory")
#define CP_WAIT1()  asm volatile("cp.async.wait_group 1;" ::: "memory")

__device__ __forceinline__ void ldsm_x4(uint32_t* r, uint32_t addr) {
    asm volatile("ldmatrix.sync.aligned.m8n8.x4.shared.b16 {%0,%1,%2,%3}, [%4];"
                 : "=r"(r[0]), "=r"(r[1]), "=r"(r[2]), "=r"(r[3]) : "r"(addr));
}
__device__ __forceinline__ void mma16816(float* d, const uint32_t* a, const uint32_t* b) {
    asm volatile(
        "mma.sync.aligned.m16n8k16.row.col.f32.bf16.bf16.f32 "
        "{%0,%1,%2,%3}, {%4,%5,%6,%7}, {%8,%9}, {%0,%1,%2,%3};"
        : "+f"(d[0]), "+f"(d[1]), "+f"(d[2]), "+f"(d[3])
        : "r"(a[0]), "r"(a[1]), "r"(a[2]), "r"(a[3]), "r"(b[0]), "r"(b[1]));
}

// ---------------------------------------------------------------------------
// bf16 mma.sync GEMM: tile 128x128x64, 8 warps (4m x 2n), 3-stage cp.async,
// ONE __syncthreads per K-iter ({wait, sync, compute, issue+commit}).
// A [M,K] K-major bf16; B [N,K] K-major bf16. C = A B^T.
// EPI: 0 proj (z=0: relu*SCALE -> g_x ; z=1: relu -> g_m)
//      2 logits (mask -> fp16 g_sh),  3 context (fp32 -> out, ld 1024)
// Stage (32KB): [0]A(16K) [16K]B(16K); rows 128B (64 bf16), XOR-swizzled.
// ---------------------------------------------------------------------------
#define STAGES 3
#define STAGE_BYTES 32768
#define DSMEM (STAGES * STAGE_BYTES + 1024)

__device__ __forceinline__ uint32_t sw_off(int row, int kb) {
    // 128B rows, kb in 16B units (0..7), XOR-swizzled within row
    return (uint32_t)(row * 128 + ((kb ^ (row & 7)) << 4));
}

template<int K, int EPI>
__global__ void __launch_bounds__(256, 2)
gemm_mma_kernel(const bf16* __restrict__ A, size_t aBS,
                const bf16* __restrict__ B, size_t bBS,
                const int* __restrict__ mask,
                float* __restrict__ outf,
                __half* __restrict__ outh,
                bf16* __restrict__ obf,
                const bf16* __restrict__ A2, const bf16* __restrict__ B2,
                bf16* __restrict__ obf2)
{
    extern __shared__ char dsm_raw[];
    __shared__ int s_mask[128];

    const int tid  = threadIdx.x;
    const int wid  = tid >> 5;
    const int lane = tid & 31;
    const int n0 = blockIdx.x * 128;
    const int m0 = blockIdx.y * 128;
    const int b  = blockIdx.z;

    const uint32_t smem0 = (s2u(dsm_raw) + 1023u) & ~1023u;

    if (EPI == 2 && tid < 128)
        s_mask[tid] = mask[(size_t)b * SK + n0 + tid];

    const bf16* Abase = A;
    const bf16* Bbase = B;
    bf16* obase = obf;
    if (EPI == 0 && b == 1) { Abase = A2; Bbase = B2; obase = obf2; }

    const bf16* Ag = Abase + (size_t)b * aBS + (size_t)m0 * K;
    const bf16* Bg = Bbase + (size_t)b * bBS + (size_t)n0 * K;

    const int NC = K / 64;

    // per-thread load slots: 4 x (row, kb); kb in 16B units 0..7
    uint32_t dsw[4];
    size_t   sof[4];
    #pragma unroll
    for (int u = 0; u < 4; u++) {
        int i = tid + u * 256;
        int r = i >> 3, kb = i & 7;
        dsw[u] = sw_off(r, kb);
        sof[u] = (size_t)r * K + kb * 8;
    }

    #define ISSUE_STAGE(kt_) do {                                        \
        uint32_t sb_ = smem0 + ((kt_) % STAGES) * STAGE_BYTES;           \
        size_t ko_ = (size_t)(kt_) * 64;                                 \
        _Pragma("unroll")                                                \
        for (int u = 0; u < 4; u++) {                                    \
            cp_async16(sb_ + dsw[u],         Ag + sof[u] + ko_);         \
            cp_async16(sb_ + dsw[u] + 16384, Bg + sof[u] + ko_);         \
        }                                                                \
    } while (0)

    ISSUE_STAGE(0); CP_COMMIT();
    ISSUE_STAGE(1); CP_COMMIT();

    const int wm = (wid & 3) * 32;
    const int wn = (wid >> 2) * 64;

    float acc[2][8][4];
    #pragma unroll
    for (int i = 0; i < 2; i++)
        #pragma unroll
        for (int j = 0; j < 8; j++)
            #pragma unroll
            for (int q = 0; q < 4; q++) acc[i][j][q] = 0.f;

    const int a_row = wm + (lane & 15);
    const int a_kb  = lane >> 4;
    const int b_row = wn + (lane & 7) + ((lane >> 4) & 1) * 8;
    const int b_kb  = (lane >> 3) & 1;

    for (int kt = 0; kt < NC; kt++) {
        CP_WAIT1();
        __syncthreads();

        const uint32_t sb = smem0 + (kt % STAGES) * STAGE_BYTES;

        #pragma unroll
        for (int ks = 0; ks < 4; ks++) {
            uint32_t af[2][4];
            #pragma unroll
            for (int mt = 0; mt < 2; mt++)
                ldsm_x4(af[mt], sb + sw_off(a_row + mt * 16, a_kb + ks * 2));
            #pragma unroll
            for (int g = 0; g < 4; g++) {
                uint32_t bfog[4];
                ldsm_x4(bfog, sb + 16384 + sw_off(b_row + g * 16, b_kb + ks * 2));
                #pragma unroll
                for (int mt = 0; mt < 2; mt++) {
                    mma16816(acc[mt][2 * g + 0], af[mt], bfog + 0);
                    mma16816(acc[mt][2 * g + 1], af[mt], bfog + 2);
                }
            }
        }

        if (kt + 2 < NC) ISSUE_STAGE(kt + 2);
        CP_COMMIT();
    }
    #undef ISSUE_STAGE

    // ------------------------- epilogue -------------------------
    const int er = lane >> 2;
    const int ec = (lane & 3) * 2;
    const float scl = (EPI == 0 && b == 0) ? SCALE : 1.0f;

    #pragma unroll
    for (int mt = 0; mt < 2; mt++) {
        #pragma unroll
        for (int nt = 0; nt < 8; nt++) {
            const int rA = m0 + wm + mt * 16 + er;
            const int rB = rA + 8;
            const int cl = wn + nt * 8 + ec;
            float v0 = acc[mt][nt][0], v1 = acc[mt][nt][1];
            float v2 = acc[mt][nt][2], v3 = acc[mt][nt][3];

            if (EPI == 0) {
                v0 = fmaxf(v0, 0.f) * scl; v1 = fmaxf(v1, 0.f) * scl;
                v2 = fmaxf(v2, 0.f) * scl; v3 = fmaxf(v3, 0.f) * scl;
                __nv_bfloat162 h0, h1;
                h0.x = __float2bfloat16_rn(v0); h0.y = __float2bfloat16_rn(v1);
                h1.x = __float2bfloat16_rn(v2); h1.y = __float2bfloat16_rn(v3);
                *(__nv_bfloat162*)(obase + (size_t)rA * ATTD + n0 + cl) = h0;
                *(__nv_bfloat162*)(obase + (size_t)rB * ATTD + n0 + cl) = h1;
            } else if (EPI == 2) {
                const int mk0 = s_mask[cl], mk1 = s_mask[cl + 1];
                float w0x = mk0 ? v0 : MASKED_LOGIT;
                float w0y = mk1 ? v1 : MASKED_LOGIT;
                float w1x = mk0 ? v2 : MASKED_LOGIT;
                float w1y = mk1 ? v3 : MASKED_LOGIT;
                size_t base = (size_t)b * SQ * SK;
                *(__half2*)(outh + base + (size_t)rA * SK + n0 + cl) =
                    __floats2half2_rn(w0x, w0y);
                *(__half2*)(outh + base + (size_t)rB * SK + n0 + cl) =
                    __floats2half2_rn(w1x, w1y);
            } else {  // EPI 3: context -> out[:, :512], row stride 1024
                float2 w0, w1;
                w0.x = v0; w0.y = v1; w1.x = v2; w1.y = v3;
                *(float2*)(outf + ((size_t)b * SQ + rA) * 1024 + n0 + cl) = w0;
                *(float2*)(outf + ((size_t)b * SQ + rB) * 1024 + n0 + cl) = w1;
            }
        }
    }
}

// ---------------------------------------------------------------------------
// inputs: fp32 -> bf16, fused with concat copy to out[:, 512:]
// ---------------------------------------------------------------------------
__global__ __launch_bounds__(256)
void conv_inputs_kernel(const float* __restrict__ src, bf16* __restrict__ dst,
                        float* __restrict__ out)
{
    const size_t i = (size_t)blockIdx.x * 256 + threadIdx.x;   // float4 index
    const size_t row = i >> 7;
    const size_t c = i & 127;
    float4 v = ((const float4*)src)[i];
    ((float4*)out)[row * 256 + 128 + c] = v;   // concat half
    __nv_bfloat162 h0, h1;
    h0.x = __float2bfloat16_rn(v.x); h0.y = __float2bfloat16_rn(v.y);
    h1.x = __float2bfloat16_rn(v.z); h1.y = __float2bfloat16_rn(v.w);
    ((__nv_bfloat162*)dst)[i * 2]     = h0;
    ((__nv_bfloat162*)dst)[i * 2 + 1] = h1;
}

// ---------------------------------------------------------------------------
// memory: fp32 [1024,512] per batch -> bf16 row-major AND bf16 transposed
// ---------------------------------------------------------------------------
__global__ __launch_bounds__(256)
void conv_memory_kernel(const float* __restrict__ src,
                        bf16* __restrict__ mem_b, bf16* __restrict__ memT)
{
    __shared__ float t[32][33];
    const int bx = blockIdx.x * 32;   // over C=512
    const int by = blockIdx.y * 32;   // over R=1024
    const size_t bo = (size_t)blockIdx.z * SK * ATTD;
    src += bo; mem_b += bo; memT += bo;

    #pragma unroll
    for (int i = threadIdx.y; i < 32; i += 8) {
        float v = src[(size_t)(by + i) * ATTD + bx + threadIdx.x];
        t[i][threadIdx.x] = v;
        mem_b[(size_t)(by + i) * ATTD + bx + threadIdx.x] = __float2bfloat16_rn(v);
    }
    __syncthreads();
    #pragma unroll
    for (int i = threadIdx.y; i < 32; i += 8)
        memT[(size_t)(bx + i) * SK + by + threadIdx.x] =
            __float2bfloat16_rn(t[threadIdx.x][i]);
}

// ---------------------------------------------------------------------------
// W [512,512] fp32 -> W^T bf16 ; z selects Wi / Wm
// ---------------------------------------------------------------------------
__global__ __launch_bounds__(256)
void convW_kernel(const float* __restrict__ Wi, const float* __restrict__ Wm,
                  bf16* __restrict__ wiT, bf16* __restrict__ wmT)
{
    __shared__ float t[32][33];
    const float* src = blockIdx.z ? Wm : Wi;
    bf16* dstT = blockIdx.z ? wmT : wiT;
    const int bx = blockIdx.x * 32;
    const int by = blockIdx.y * 32;
    #pragma unroll
    for (int i = threadIdx.y; i < 32; i += 8)
        t[i][threadIdx.x] = src[(size_t)(by + i) * ATTD + bx + threadIdx.x];
    __syncthreads();
    #pragma unroll
    for (int i = threadIdx.y; i < 32; i += 8)
        dstT[(size_t)(bx + i) * ATTD + by + threadIdx.x] =
            __float2bfloat16_rn(t[threadIdx.x][i]);
}

// ---------------------------------------------------------------------------
// row softmax over SK=1024 on fp16 logits; writes probs bf16
// ---------------------------------------------------------------------------
__global__ __launch_bounds__(256)
void softmax_kernel()
{
    const size_t row = blockIdx.x;
    const __half* p = g_sh + row * SK;
    const int tid = threadIdx.x;
    const int lane = tid & 31, wid = tid >> 5;

    uint2 raw = ((const uint2*)p)[tid];
    __half2 a = *(__half2*)&raw.x;
    __half2 c = *(__half2*)&raw.y;
    float v0 = __low2float(a), v1 = __high2float(a);
    float v2 = __low2float(c), v3 = __high2float(c);

    float mx = fmaxf(fmaxf(v0, v1), fmaxf(v2, v3));
    #pragma unroll
    for (int o = 16; o > 0; o >>= 1) mx = fmaxf(mx, __shfl_xor_sync(0xffffffffu, mx, o));

    __shared__ float sm[8], ss[8];
    if (lane == 0) sm[wid] = mx;
    __syncthreads();
    float m = sm[0];
    #pragma unroll
    for (int w = 1; w < 8; w++) m = fmaxf(m, sm[w]);

    float e0 = __expf(v0 - m), e1 = __expf(v1 - m);
    float e2 = __expf(v2 - m), e3 = __expf(v3 - m);
    float s = (e0 + e1) + (e2 + e3);
    #pragma unroll
    for (int o = 16; o > 0; o >>= 1) s += __shfl_xor_sync(0xffffffffu, s, o);
    if (lane == 0) ss[wid] = s;
    __syncthreads();
    float tot = 0.f;
    #pragma unroll
    for (int w = 0; w < 8; w++) tot += ss[w];
    const float inv = 1.0f / tot;

    __nv_bfloat162 h0, h1;
    h0.x = __float2bfloat16_rn(e0 * inv); h0.y = __float2bfloat16_rn(e1 * inv);
    h1.x = __float2bfloat16_rn(e2 * inv); h1.y = __float2bfloat16_rn(e3 * inv);
    __nv_bfloat162* ph = (__nv_bfloat162*)(g_p + row * SK);
    ph[tid * 2] = h0; ph[tid * 2 + 1] = h1;
}

// ---------------------------------------------------------------------------
extern "C" void kernel_launch(void* const* d_in, const int* in_sizes, int n_in,
                              void* d_out, int out_size)
{
    const float* inputs = (const float*)d_in[0];
    const float* memory = (const float*)d_in[1];
    const int*   mask   = (const int*)d_in[2];
    const float* Wi     = (const float*)d_in[3];
    const float* Wm     = (const float*)d_in[4];
    float* out = (float*)d_out;

    cudaFuncSetAttribute(gemm_mma_kernel<512, 0>,  cudaFuncAttributeMaxDynamicSharedMemorySize, DSMEM);
    cudaFuncSetAttribute(gemm_mma_kernel<512, 2>,  cudaFuncAttributeMaxDynamicSharedMemorySize, DSMEM);
    cudaFuncSetAttribute(gemm_mma_kernel<1024, 3>, cudaFuncAttributeMaxDynamicSharedMemorySize, DSMEM);

    bf16 *in_b, *mem_b, *wiT, *wmT, *x_b, *m_b, *memT, *p_b;
    __half* sh;
    cudaGetSymbolAddress((void**)&in_b, g_in_b);
    cudaGetSymbolAddress((void**)&mem_b, g_mem_b);
    cudaGetSymbolAddress((void**)&wiT, g_wiT);
    cudaGetSymbolAddress((void**)&wmT, g_wmT);
    cudaGetSymbolAddress((void**)&x_b, g_x);
    cudaGetSymbolAddress((void**)&m_b, g_m);
    cudaGetSymbolAddress((void**)&memT, g_memT);
    cudaGetSymbolAddress((void**)&p_b, g_p);
    cudaGetSymbolAddress((void**)&sh, g_sh);

    // 1) conversions (concat fused into inputs convert; both W in one launch)
    conv_inputs_kernel<<<16384, 256>>>(inputs, in_b, out);
    conv_memory_kernel<<<dim3(16, 32, 32), dim3(32, 8)>>>(memory, mem_b, memT);
    convW_kernel<<<dim3(16, 16, 2), dim3(32, 8)>>>(Wi, Wm, wiT, wmT);

    // 2) both projections in ONE launch (z=0: x path, z=1: m path)
    gemm_mma_kernel<512, 0><<<dim3(4, 256, 2), 256, DSMEM>>>(
        in_b, 0, wiT, 0, nullptr, nullptr, nullptr, x_b, mem_b, wmT, m_b);

    // 3) logits: per batch x @ m^T (scale folded into x), masked -> fp16 g_sh
    gemm_mma_kernel<512, 2><<<dim3(8, 8, 32), 256, DSMEM>>>(
        x_b, (size_t)SQ * ATTD, m_b, (size_t)SK * ATTD, mask,
        nullptr, sh, nullptr, nullptr, nullptr, nullptr);

    // 4) softmax -> p bf16
    softmax_kernel<<<BATCH * SQ, 256>>>();

    // 5) context: per batch P @ memory -> out[:, :512]
    gemm_mma_kernel<1024, 3><<<dim3(4, 8, 32), 256, DSMEM>>>(
        p_b, (size_t)SQ * SK, memT, (size_t)ATTD * SK, nullptr,
        out, nullptr, nullptr, nullptr, nullptr, nullptr);
}

// round 7
// speedup vs baseline: 6.6482x; 1.0742x over previous
#include <cuda_runtime.h>
#include <cuda_bf16.h>
#include <cstdint>

#define BATCH 32
#define SQ 1024
#define SK 1024
#define ATTD 512
#define SCALE 0.044194173824159216f   // 1/sqrt(512)

typedef __nv_bfloat16 bf16;

// ---------------------------------------------------------------------------
// Scratch (static device globals — no runtime allocation)
// ---------------------------------------------------------------------------
__device__ bf16 g_in_b [(size_t)BATCH * SQ * ATTD];    // inputs bf16
__device__ bf16 g_mem_b[(size_t)BATCH * SK * ATTD];    // memory bf16
__device__ bf16 g_wiT  [(size_t)ATTD * ATTD];          // Wi^T bf16
__device__ bf16 g_wmT  [(size_t)ATTD * ATTD];          // Wm^T bf16
__device__ bf16 g_x    [(size_t)BATCH * SQ * ATTD];    // relu(in@Wi)*scale
__device__ bf16 g_m    [(size_t)BATCH * SK * ATTD];    // relu(mem@Wm)
__device__ bf16 g_memT [(size_t)BATCH * ATTD * SK];    // memory^T per batch
__device__ bf16 g_p    [(size_t)BATCH * SQ * SK];      // exp(logits), masked->0
__device__ float g_rinv[(size_t)BATCH * SQ];           // 1 / rowsum(g_p)

// ---------------------------------------------------------------------------
// PTX helpers
// ---------------------------------------------------------------------------
__device__ __forceinline__ uint32_t s2u(const void* p) {
    return (uint32_t)__cvta_generic_to_shared(p);
}
__device__ __forceinline__ void cp_async16(uint32_t dst, const void* src) {
    asm volatile("cp.async.cg.shared.global [%0], [%1], 16;" :: "r"(dst), "l"(src));
}
#define CP_COMMIT() asm volatile("cp.async.commit_group;" ::: "memory")
#define CP_WAIT1()  asm volatile("cp.async.wait_group 1;" ::: "memory")

__device__ __forceinline__ void ldsm_x4(uint32_t* r, uint32_t addr) {
    asm volatile("ldmatrix.sync.aligned.m8n8.x4.shared.b16 {%0,%1,%2,%3}, [%4];"
                 : "=r"(r[0]), "=r"(r[1]), "=r"(r[2]), "=r"(r[3]) : "r"(addr));
}
__device__ __forceinline__ void mma16816(float* d, const uint32_t* a, const uint32_t* b) {
    asm volatile(
        "mma.sync.aligned.m16n8k16.row.col.f32.bf16.bf16.f32 "
        "{%0,%1,%2,%3}, {%4,%5,%6,%7}, {%8,%9}, {%0,%1,%2,%3};"
        : "+f"(d[0]), "+f"(d[1]), "+f"(d[2]), "+f"(d[3])
        : "r"(a[0]), "r"(a[1]), "r"(a[2]), "r"(a[3]), "r"(b[0]), "r"(b[1]));
}

// ---------------------------------------------------------------------------
// bf16 mma.sync GEMM: tile 128x128x64, 8 warps (4m x 2n), 3-stage cp.async,
// one __syncthreads per K-iter.  C = A B^T.
// EPI: 0 proj (z=0: relu*SCALE -> obf ; z=1: relu -> obf2)
//      2 logits (mask -> exp -> bf16 obf),  3 context (fp32 * rinv -> outf)
// ---------------------------------------------------------------------------
#define STAGES 3
#define STAGE_BYTES 32768
#define DSMEM (STAGES * STAGE_BYTES + 1024)

__device__ __forceinline__ uint32_t sw_off(int row, int kb) {
    return (uint32_t)(row * 128 + ((kb ^ (row & 7)) << 4));
}

template<int K, int EPI>
__global__ void __launch_bounds__(256, 2)
gemm_mma_kernel(const bf16* __restrict__ A, size_t aBS,
                const bf16* __restrict__ B, size_t bBS,
                const int* __restrict__ mask,
                const float* __restrict__ rinv,
                float* __restrict__ outf,
                bf16* __restrict__ obf,
                const bf16* __restrict__ A2, const bf16* __restrict__ B2,
                bf16* __restrict__ obf2)
{
    extern __shared__ char dsm_raw[];
    __shared__ int   s_mask[128];
    __shared__ float s_rinv[128];

    const int tid  = threadIdx.x;
    const int wid  = tid >> 5;
    const int lane = tid & 31;
    const int n0 = blockIdx.x * 128;
    const int m0 = blockIdx.y * 128;
    const int b  = blockIdx.z;

    const uint32_t smem0 = (s2u(dsm_raw) + 1023u) & ~1023u;

    if (EPI == 2 && tid < 128)
        s_mask[tid] = mask[(size_t)b * SK + n0 + tid];
    if (EPI == 3 && tid < 128)
        s_rinv[tid] = rinv[(size_t)b * SQ + m0 + tid];

    const bf16* Abase = A;
    const bf16* Bbase = B;
    bf16* obase = obf;
    if (EPI == 0 && b == 1) { Abase = A2; Bbase = B2; obase = obf2; }

    const bf16* Ag = Abase + (size_t)b * aBS + (size_t)m0 * K;
    const bf16* Bg = Bbase + (size_t)b * bBS + (size_t)n0 * K;

    const int NC = K / 64;

    uint32_t dsw[4];
    size_t   sof[4];
    #pragma unroll
    for (int u = 0; u < 4; u++) {
        int i = tid + u * 256;
        int r = i >> 3, kb = i & 7;
        dsw[u] = sw_off(r, kb);
        sof[u] = (size_t)r * K + kb * 8;
    }

    #define ISSUE_STAGE(kt_) do {                                        \
        uint32_t sb_ = smem0 + ((kt_) % STAGES) * STAGE_BYTES;           \
        size_t ko_ = (size_t)(kt_) * 64;                                 \
        _Pragma("unroll")                                                \
        for (int u = 0; u < 4; u++) {                                    \
            cp_async16(sb_ + dsw[u],         Ag + sof[u] + ko_);         \
            cp_async16(sb_ + dsw[u] + 16384, Bg + sof[u] + ko_);         \
        }                                                                \
    } while (0)

    ISSUE_STAGE(0); CP_COMMIT();
    ISSUE_STAGE(1); CP_COMMIT();

    const int wm = (wid & 3) * 32;
    const int wn = (wid >> 2) * 64;

    float acc[2][8][4];
    #pragma unroll
    for (int i = 0; i < 2; i++)
        #pragma unroll
        for (int j = 0; j < 8; j++)
            #pragma unroll
            for (int q = 0; q < 4; q++) acc[i][j][q] = 0.f;

    const int a_row = wm + (lane & 15);
    const int a_kb  = lane >> 4;
    const int b_row = wn + (lane & 7) + ((lane >> 4) & 1) * 8;
    const int b_kb  = (lane >> 3) & 1;

    for (int kt = 0; kt < NC; kt++) {
        CP_WAIT1();
        __syncthreads();

        const uint32_t sb = smem0 + (kt % STAGES) * STAGE_BYTES;

        #pragma unroll
        for (int ks = 0; ks < 4; ks++) {
            uint32_t af[2][4];
            #pragma unroll
            for (int mt = 0; mt < 2; mt++)
                ldsm_x4(af[mt], sb + sw_off(a_row + mt * 16, a_kb + ks * 2));
            #pragma unroll
            for (int g = 0; g < 4; g++) {
                uint32_t bfog[4];
                ldsm_x4(bfog, sb + 16384 + sw_off(b_row + g * 16, b_kb + ks * 2));
                #pragma unroll
                for (int mt = 0; mt < 2; mt++) {
                    mma16816(acc[mt][2 * g + 0], af[mt], bfog + 0);
                    mma16816(acc[mt][2 * g + 1], af[mt], bfog + 2);
                }
            }
        }

        if (kt + 2 < NC) ISSUE_STAGE(kt + 2);
        CP_COMMIT();
    }
    #undef ISSUE_STAGE

    // ------------------------- epilogue -------------------------
    const int er = lane >> 2;
    const int ec = (lane & 3) * 2;
    const float scl = (EPI == 0 && b == 0) ? SCALE : 1.0f;

    #pragma unroll
    for (int mt = 0; mt < 2; mt++) {
        #pragma unroll
        for (int nt = 0; nt < 8; nt++) {
            const int rA = m0 + wm + mt * 16 + er;
            const int rB = rA + 8;
            const int cl = wn + nt * 8 + ec;
            float v0 = acc[mt][nt][0], v1 = acc[mt][nt][1];
            float v2 = acc[mt][nt][2], v3 = acc[mt][nt][3];

            if (EPI == 0) {
                v0 = fmaxf(v0, 0.f) * scl; v1 = fmaxf(v1, 0.f) * scl;
                v2 = fmaxf(v2, 0.f) * scl; v3 = fmaxf(v3, 0.f) * scl;
                __nv_bfloat162 h0, h1;
                h0.x = __float2bfloat16_rn(v0); h0.y = __float2bfloat16_rn(v1);
                h1.x = __float2bfloat16_rn(v2); h1.y = __float2bfloat16_rn(v3);
                *(__nv_bfloat162*)(obase + (size_t)rA * ATTD + n0 + cl) = h0;
                *(__nv_bfloat162*)(obase + (size_t)rB * ATTD + n0 + cl) = h1;
            } else if (EPI == 2) {
                // exp(logit), masked -> exactly 0. No max-subtraction needed:
                // logits are small (relu'd operands, |logit| < ~5); fp32 exp safe.
                const int mk0 = s_mask[cl], mk1 = s_mask[cl + 1];
                float e0 = mk0 ? __expf(v0) : 0.f;
                float e1 = mk1 ? __expf(v1) : 0.f;
                float e2 = mk0 ? __expf(v2) : 0.f;
                float e3 = mk1 ? __expf(v3) : 0.f;
                __nv_bfloat162 h0, h1;
                h0.x = __float2bfloat16_rn(e0); h0.y = __float2bfloat16_rn(e1);
                h1.x = __float2bfloat16_rn(e2); h1.y = __float2bfloat16_rn(e3);
                size_t base = (size_t)b * SQ * SK;
                *(__nv_bfloat162*)(obf + base + (size_t)rA * SK + n0 + cl) = h0;
                *(__nv_bfloat162*)(obf + base + (size_t)rB * SK + n0 + cl) = h1;
            } else {  // EPI 3: context * rinv -> out[:, :512], row stride 1024
                const float iA = s_rinv[wm + mt * 16 + er];
                const float iB = s_rinv[wm + mt * 16 + er + 8];
                float2 w0, w1;
                w0.x = v0 * iA; w0.y = v1 * iA;
                w1.x = v2 * iB; w1.y = v3 * iB;
                *(float2*)(outf + ((size_t)b * SQ + rA) * 1024 + n0 + cl) = w0;
                *(float2*)(outf + ((size_t)b * SQ + rB) * 1024 + n0 + cl) = w1;
            }
        }
    }
}

// ---------------------------------------------------------------------------
// rowsum: one warp per q-row of g_p; writes 1/sum (fp32). Sums the ROUNDED
// bf16 values that the context GEMM consumes -> consistent normalization.
// ---------------------------------------------------------------------------
__global__ __launch_bounds__(256)
void rowsum_kernel()
{
    const int warp = threadIdx.x >> 5;
    const int lane = threadIdx.x & 31;
    const size_t row = (size_t)blockIdx.x * 8 + warp;
    const uint4* p = (const uint4*)(g_p + row * SK);   // 128 uint4 per row

    float s = 0.f;
    #pragma unroll
    for (int it = 0; it < 4; it++) {
        uint4 v = p[lane + it * 32];
        const __nv_bfloat162* h = (const __nv_bfloat162*)&v;
        #pragma unroll
        for (int j = 0; j < 4; j++) {
            float2 f = __bfloat1622float2(h[j]);
            s += f.x + f.y;
        }
    }
    #pragma unroll
    for (int o = 16; o > 0; o >>= 1) s += __shfl_xor_sync(0xffffffffu, s, o);
    if (lane == 0) g_rinv[row] = 1.0f / s;
}

// ---------------------------------------------------------------------------
// inputs: fp32 -> bf16, fused with concat copy to out[:, 512:]
// ---------------------------------------------------------------------------
__global__ __launch_bounds__(256)
void conv_inputs_kernel(const float* __restrict__ src, bf16* __restrict__ dst,
                        float* __restrict__ out)
{
    const size_t i = (size_t)blockIdx.x * 256 + threadIdx.x;   // float4 index
    const size_t row = i >> 7;
    const size_t c = i & 127;
    float4 v = ((const float4*)src)[i];
    ((float4*)out)[row * 256 + 128 + c] = v;   // concat half
    __nv_bfloat162 h0, h1;
    h0.x = __float2bfloat16_rn(v.x); h0.y = __float2bfloat16_rn(v.y);
    h1.x = __float2bfloat16_rn(v.z); h1.y = __float2bfloat16_rn(v.w);
    ((__nv_bfloat162*)dst)[i * 2]     = h0;
    ((__nv_bfloat162*)dst)[i * 2 + 1] = h1;
}

// ---------------------------------------------------------------------------
// memory: fp32 [1024,512] per batch -> bf16 row-major AND bf16 transposed
// ---------------------------------------------------------------------------
__global__ __launch_bounds__(256)
void conv_memory_kernel(const float* __restrict__ src,
                        bf16* __restrict__ mem_b, bf16* __restrict__ memT)
{
    __shared__ float t[32][33];
    const int bx = blockIdx.x * 32;   // over C=512
    const int by = blockIdx.y * 32;   // over R=1024
    const size_t bo = (size_t)blockIdx.z * SK * ATTD;
    src += bo; mem_b += bo; memT += bo;

    #pragma unroll
    for (int i = threadIdx.y; i < 32; i += 8) {
        float v = src[(size_t)(by + i) * ATTD + bx + threadIdx.x];
        t[i][threadIdx.x] = v;
        mem_b[(size_t)(by + i) * ATTD + bx + threadIdx.x] = __float2bfloat16_rn(v);
    }
    __syncthreads();
    #pragma unroll
    for (int i = threadIdx.y; i < 32; i += 8)
        memT[(size_t)(bx + i) * SK + by + threadIdx.x] =
            __float2bfloat16_rn(t[threadIdx.x][i]);
}

// ---------------------------------------------------------------------------
// W [512,512] fp32 -> W^T bf16 ; z selects Wi / Wm
// ---------------------------------------------------------------------------
__global__ __launch_bounds__(256)
void convW_kernel(const float* __restrict__ Wi, const float* __restrict__ Wm,
                  bf16* __restrict__ wiT, bf16* __restrict__ wmT)
{
    __shared__ float t[32][33];
    const float* src = blockIdx.z ? Wm : Wi;
    bf16* dstT = blockIdx.z ? wmT : wiT;
    const int bx = blockIdx.x * 32;
    const int by = blockIdx.y * 32;
    #pragma unroll
    for (int i = threadIdx.y; i < 32; i += 8)
        t[i][threadIdx.x] = src[(size_t)(by + i) * ATTD + bx + threadIdx.x];
    __syncthreads();
    #pragma unroll
    for (int i = threadIdx.y; i < 32; i += 8)
        dstT[(size_t)(bx + i) * ATTD + by + threadIdx.x] =
            __float2bfloat16_rn(t[threadIdx.x][i]);
}

// ---------------------------------------------------------------------------
extern "C" void kernel_launch(void* const* d_in, const int* in_sizes, int n_in,
                              void* d_out, int out_size)
{
    const float* inputs = (const float*)d_in[0];
    const float* memory = (const float*)d_in[1];
    const int*   mask   = (const int*)d_in[2];
    const float* Wi     = (const float*)d_in[3];
    const float* Wm     = (const float*)d_in[4];
    float* out = (float*)d_out;

    cudaFuncSetAttribute(gemm_mma_kernel<512, 0>,  cudaFuncAttributeMaxDynamicSharedMemorySize, DSMEM);
    cudaFuncSetAttribute(gemm_mma_kernel<512, 2>,  cudaFuncAttributeMaxDynamicSharedMemorySize, DSMEM);
    cudaFuncSetAttribute(gemm_mma_kernel<1024, 3>, cudaFuncAttributeMaxDynamicSharedMemorySize, DSMEM);

    bf16 *in_b, *mem_b, *wiT, *wmT, *x_b, *m_b, *memT, *p_b;
    float* rinv;
    cudaGetSymbolAddress((void**)&in_b, g_in_b);
    cudaGetSymbolAddress((void**)&mem_b, g_mem_b);
    cudaGetSymbolAddress((void**)&wiT, g_wiT);
    cudaGetSymbolAddress((void**)&wmT, g_wmT);
    cudaGetSymbolAddress((void**)&x_b, g_x);
    cudaGetSymbolAddress((void**)&m_b, g_m);
    cudaGetSymbolAddress((void**)&memT, g_memT);
    cudaGetSymbolAddress((void**)&p_b, g_p);
    cudaGetSymbolAddress((void**)&rinv, g_rinv);

    // 1) conversions (concat fused into inputs convert; both W in one launch)
    conv_inputs_kernel<<<16384, 256>>>(inputs, in_b, out);
    conv_memory_kernel<<<dim3(16, 32, 32), dim3(32, 8)>>>(memory, mem_b, memT);
    convW_kernel<<<dim3(16, 16, 2), dim3(32, 8)>>>(Wi, Wm, wiT, wmT);

    // 2) both projections in ONE launch (z=0: x = relu(in@Wi)*SCALE, z=1: m = relu(mem@Wm))
    gemm_mma_kernel<512, 0><<<dim3(4, 256, 2), 256, DSMEM>>>(
        in_b, 0, wiT, 0, nullptr, nullptr, nullptr, x_b, mem_b, wmT, m_b);

    // 3) logits -> masked exp -> g_p (bf16); no separate softmax pass
    gemm_mma_kernel<512, 2><<<dim3(8, 8, 32), 256, DSMEM>>>(
        x_b, (size_t)SQ * ATTD, m_b, (size_t)SK * ATTD, mask, nullptr,
        nullptr, p_b, nullptr, nullptr, nullptr);

    // 4) per-row reciprocal sums
    rowsum_kernel<<<BATCH * SQ / 8, 256>>>();

    // 5) context: (P @ memory) * rinv -> out[:, :512]
    gemm_mma_kernel<1024, 3><<<dim3(4, 8, 32), 256, DSMEM>>>(
        p_b, (size_t)SQ * SK, memT, (size_t)ATTD * SK, nullptr, rinv,
        out, nullptr, nullptr, nullptr, nullptr);
}

// round 8
// speedup vs baseline: 8.9147x; 1.3409x over previous
#include <cuda_runtime.h>
#include <cuda_bf16.h>
#include <cstdint>

#define BATCH 32
#define SQ 1024
#define SK 1024
#define ATTD 512
#define SCALE 0.044194173824159216f   // 1/sqrt(512)

typedef __nv_bfloat16 bf16;

// ---------------------------------------------------------------------------
// Scratch (static device globals — no runtime allocation)
// ---------------------------------------------------------------------------
__device__ bf16 g_in_b [(size_t)BATCH * SQ * ATTD];    // inputs bf16
__device__ bf16 g_mem_c[(size_t)BATCH * SK * ATTD];    // gathered (unmasked) memory bf16
__device__ bf16 g_wiT  [(size_t)ATTD * ATTD];          // Wi^T bf16
__device__ bf16 g_wmT  [(size_t)ATTD * ATTD];          // Wm^T bf16
__device__ bf16 g_x    [(size_t)BATCH * SQ * ATTD];    // relu(in@Wi)*scale
__device__ bf16 g_m    [(size_t)BATCH * SK * ATTD];    // relu(mem_c@Wm) (compact rows)
__device__ bf16 g_memT [(size_t)BATCH * ATTD * SK];    // gathered memory^T per batch
__device__ bf16 g_p    [(size_t)BATCH * SQ * SK];      // exp(logits) compact, masked->0
__device__ float g_rinv[(size_t)BATCH * SQ];           // 1 / rowsum(g_p)
__device__ int  g_idx  [(size_t)BATCH * SK];           // compact -> original key index
__device__ int  g_nc   [BATCH];                        // # unmasked keys
__device__ int  g_ncp  [BATCH];                        // nc padded to 128

// ---------------------------------------------------------------------------
// PTX helpers
// ---------------------------------------------------------------------------
__device__ __forceinline__ uint32_t s2u(const void* p) {
    return (uint32_t)__cvta_generic_to_shared(p);
}
__device__ __forceinline__ void cp_async16(uint32_t dst, const void* src) {
    asm volatile("cp.async.cg.shared.global [%0], [%1], 16;" :: "r"(dst), "l"(src));
}
#define CP_COMMIT() asm volatile("cp.async.commit_group;" ::: "memory")
#define CP_WAIT1()  asm volatile("cp.async.wait_group 1;" ::: "memory")

__device__ __forceinline__ void ldsm_x4(uint32_t* r, uint32_t addr) {
    asm volatile("ldmatrix.sync.aligned.m8n8.x4.shared.b16 {%0,%1,%2,%3}, [%4];"
                 : "=r"(r[0]), "=r"(r[1]), "=r"(r[2]), "=r"(r[3]) : "r"(addr));
}
__device__ __forceinline__ void mma16816(float* d, const uint32_t* a, const uint32_t* b) {
    asm volatile(
        "mma.sync.aligned.m16n8k16.row.col.f32.bf16.bf16.f32 "
        "{%0,%1,%2,%3}, {%4,%5,%6,%7}, {%8,%9}, {%0,%1,%2,%3};"
        : "+f"(d[0]), "+f"(d[1]), "+f"(d[2]), "+f"(d[3])
        : "r"(a[0]), "r"(a[1]), "r"(a[2]), "r"(a[3]), "r"(b[0]), "r"(b[1]));
}

// ---------------------------------------------------------------------------
// mask prefix scan: per batch builds idx list (ascending), nc, nc_pad(128)
// ---------------------------------------------------------------------------
__global__ __launch_bounds__(1024)
void mask_scan_kernel(const int* __restrict__ mask)
{
    __shared__ int s[1024];
    const int b = blockIdx.x;
    const int t = threadIdx.x;
    const int v = mask[(size_t)b * SK + t] != 0;
    s[t] = v;
    __syncthreads();
    #pragma unroll
    for (int off = 1; off < 1024; off <<= 1) {
        int x = 0;
        if (t >= off) x = s[t - off];
        __syncthreads();
        if (t >= off) s[t] += x;
        __syncthreads();
    }
    if (v) g_idx[(size_t)b * SK + s[t] - 1] = t;
    if (t == 1023) {
        g_nc[b]  = s[1023];
        g_ncp[b] = (s[1023] + 127) & ~127;
    }
}

// ---------------------------------------------------------------------------
// bf16 mma.sync GEMM: tile 128x128x64, 8 warps (4m x 2n), 3-stage cp.async.
// EPI: 0 proj (z=0: relu*SCALE -> obf ; z=1: relu -> obf2, compact-M early exit)
//      2 logits (compact-N early exit; exp, zero pad -> bf16 obf)
//      3 context (runtime K = ncp[b]; fp32 * rinv -> outf)
// ---------------------------------------------------------------------------
#define STAGES 3
#define STAGE_BYTES 32768
#define DSMEM (STAGES * STAGE_BYTES + 1024)

__device__ __forceinline__ uint32_t sw_off(int row, int kb) {
    return (uint32_t)(row * 128 + ((kb ^ (row & 7)) << 4));
}

template<int K, int EPI>
__global__ void __launch_bounds__(256, 2)
gemm_mma_kernel(const bf16* __restrict__ A, size_t aBS,
                const bf16* __restrict__ B, size_t bBS,
                const float* __restrict__ rinv,
                float* __restrict__ outf,
                bf16* __restrict__ obf,
                const bf16* __restrict__ A2, const bf16* __restrict__ B2,
                bf16* __restrict__ obf2)
{
    extern __shared__ char dsm_raw[];
    __shared__ float s_rinv[128];

    const int tid  = threadIdx.x;
    const int wid  = tid >> 5;
    const int lane = tid & 31;
    const int n0 = blockIdx.x * 128;
    const int m0 = blockIdx.y * 128;
    const int b  = blockIdx.z;

    // ---- compaction-driven early exits / runtime K ----
    int nc = 0;
    if (EPI == 0) {
        if (b == 1 && (m0 & (SK - 1)) >= g_ncp[m0 >> 10]) return;
    } else if (EPI == 2) {
        if (n0 >= g_ncp[b]) return;
        nc = g_nc[b];
    }
    int NC = K / 64;
    if (EPI == 3) NC = g_ncp[b] >> 6;

    const uint32_t smem0 = (s2u(dsm_raw) + 1023u) & ~1023u;

    if (EPI == 3 && tid < 128)
        s_rinv[tid] = rinv[(size_t)b * SQ + m0 + tid];

    const bf16* Abase = A;
    const bf16* Bbase = B;
    bf16* obase = obf;
    if (EPI == 0 && b == 1) { Abase = A2; Bbase = B2; obase = obf2; }

    const bf16* Ag = Abase + (size_t)b * aBS + (size_t)m0 * K;
    const bf16* Bg = Bbase + (size_t)b * bBS + (size_t)n0 * K;

    uint32_t dsw[4];
    size_t   sof[4];
    #pragma unroll
    for (int u = 0; u < 4; u++) {
        int i = tid + u * 256;
        int r = i >> 3, kb = i & 7;
        dsw[u] = sw_off(r, kb);
        sof[u] = (size_t)r * K + kb * 8;
    }

    #define ISSUE_STAGE(kt_) do {                                        \
        uint32_t sb_ = smem0 + ((kt_) % STAGES) * STAGE_BYTES;           \
        size_t ko_ = (size_t)(kt_) * 64;                                 \
        _Pragma("unroll")                                                \
        for (int u = 0; u < 4; u++) {                                    \
            cp_async16(sb_ + dsw[u],         Ag + sof[u] + ko_);         \
            cp_async16(sb_ + dsw[u] + 16384, Bg + sof[u] + ko_);         \
        }                                                                \
    } while (0)

    ISSUE_STAGE(0); CP_COMMIT();
    ISSUE_STAGE(1); CP_COMMIT();      // may prefetch past NC; addresses in-bounds

    const int wm = (wid & 3) * 32;
    const int wn = (wid >> 2) * 64;

    float acc[2][8][4];
    #pragma unroll
    for (int i = 0; i < 2; i++)
        #pragma unroll
        for (int j = 0; j < 8; j++)
            #pragma unroll
            for (int q = 0; q < 4; q++) acc[i][j][q] = 0.f;

    const int a_row = wm + (lane & 15);
    const int a_kb  = lane >> 4;
    const int b_row = wn + (lane & 7) + ((lane >> 4) & 1) * 8;
    const int b_kb  = (lane >> 3) & 1;

    for (int kt = 0; kt < NC; kt++) {
        CP_WAIT1();
        __syncthreads();

        const uint32_t sb = smem0 + (kt % STAGES) * STAGE_BYTES;

        #pragma unroll
        for (int ks = 0; ks < 4; ks++) {
            uint32_t af[2][4];
            #pragma unroll
            for (int mt = 0; mt < 2; mt++)
                ldsm_x4(af[mt], sb + sw_off(a_row + mt * 16, a_kb + ks * 2));
            #pragma unroll
            for (int g = 0; g < 4; g++) {
                uint32_t bfog[4];
                ldsm_x4(bfog, sb + 16384 + sw_off(b_row + g * 16, b_kb + ks * 2));
                #pragma unroll
                for (int mt = 0; mt < 2; mt++) {
                    mma16816(acc[mt][2 * g + 0], af[mt], bfog + 0);
                    mma16816(acc[mt][2 * g + 1], af[mt], bfog + 2);
                }
            }
        }

        if (kt + 2 < NC) ISSUE_STAGE(kt + 2);
        CP_COMMIT();
    }
    #undef ISSUE_STAGE

    // ------------------------- epilogue -------------------------
    const int er = lane >> 2;
    const int ec = (lane & 3) * 2;
    const float scl = (EPI == 0 && b == 0) ? SCALE : 1.0f;

    #pragma unroll
    for (int mt = 0; mt < 2; mt++) {
        #pragma unroll
        for (int nt = 0; nt < 8; nt++) {
            const int rA = m0 + wm + mt * 16 + er;
            const int rB = rA + 8;
            const int cl = wn + nt * 8 + ec;
            float v0 = acc[mt][nt][0], v1 = acc[mt][nt][1];
            float v2 = acc[mt][nt][2], v3 = acc[mt][nt][3];

            if (EPI == 0) {
                v0 = fmaxf(v0, 0.f) * scl; v1 = fmaxf(v1, 0.f) * scl;
                v2 = fmaxf(v2, 0.f) * scl; v3 = fmaxf(v3, 0.f) * scl;
                __nv_bfloat162 h0, h1;
                h0.x = __float2bfloat16_rn(v0); h0.y = __float2bfloat16_rn(v1);
                h1.x = __float2bfloat16_rn(v2); h1.y = __float2bfloat16_rn(v3);
                *(__nv_bfloat162*)(obase + (size_t)rA * ATTD + n0 + cl) = h0;
                *(__nv_bfloat162*)(obase + (size_t)rB * ATTD + n0 + cl) = h1;
            } else if (EPI == 2) {
                // exp(logit); compact keys are all unmasked; zero the pad region
                // (pad rows are zero-projections -> logit 0 -> exp=1 otherwise).
                const bool c0 = (n0 + cl)     < nc;
                const bool c1 = (n0 + cl + 1) < nc;
                float e0 = c0 ? __expf(v0) : 0.f;
                float e1 = c1 ? __expf(v1) : 0.f;
                float e2 = c0 ? __expf(v2) : 0.f;
                float e3 = c1 ? __expf(v3) : 0.f;
                __nv_bfloat162 h0, h1;
                h0.x = __float2bfloat16_rn(e0); h0.y = __float2bfloat16_rn(e1);
                h1.x = __float2bfloat16_rn(e2); h1.y = __float2bfloat16_rn(e3);
                size_t base = (size_t)b * SQ * SK;
                *(__nv_bfloat162*)(obf + base + (size_t)rA * SK + n0 + cl) = h0;
                *(__nv_bfloat162*)(obf + base + (size_t)rB * SK + n0 + cl) = h1;
            } else {  // EPI 3: context * rinv -> out[:, :512], row stride 1024
                const float iA = s_rinv[wm + mt * 16 + er];
                const float iB = s_rinv[wm + mt * 16 + er + 8];
                float2 w0, w1;
                w0.x = v0 * iA; w0.y = v1 * iA;
                w1.x = v2 * iB; w1.y = v3 * iB;
                *(float2*)(outf + ((size_t)b * SQ + rA) * 1024 + n0 + cl) = w0;
                *(float2*)(outf + ((size_t)b * SQ + rB) * 1024 + n0 + cl) = w1;
            }
        }
    }
}

// ---------------------------------------------------------------------------
// rowsum over compact region; writes 1/sum (fp32)
// ---------------------------------------------------------------------------
__global__ __launch_bounds__(256)
void rowsum_kernel()
{
    const int warp = threadIdx.x >> 5;
    const int lane = threadIdx.x & 31;
    const size_t row = (size_t)blockIdx.x * 8 + warp;
    const int np = g_ncp[row >> 10];           // uint4 count = np/8
    const uint4* p = (const uint4*)(g_p + row * SK);

    float s = 0.f;
    const int n4 = np >> 3;
    for (int u = lane; u < n4; u += 32) {
        uint4 v = p[u];
        const __nv_bfloat162* h = (const __nv_bfloat162*)&v;
        #pragma unroll
        for (int j = 0; j < 4; j++) {
            float2 f = __bfloat1622float2(h[j]);
            s += f.x + f.y;
        }
    }
    #pragma unroll
    for (int o = 16; o > 0; o >>= 1) s += __shfl_xor_sync(0xffffffffu, s, o);
    if (lane == 0) g_rinv[row] = 1.0f / s;
}

// ---------------------------------------------------------------------------
// inputs: fp32 -> bf16, fused with concat copy to out[:, 512:]
// ---------------------------------------------------------------------------
__global__ __launch_bounds__(256)
void conv_inputs_kernel(const float* __restrict__ src, bf16* __restrict__ dst,
                        float* __restrict__ out)
{
    const size_t i = (size_t)blockIdx.x * 256 + threadIdx.x;
    const size_t row = i >> 7;
    const size_t c = i & 127;
    float4 v = ((const float4*)src)[i];
    ((float4*)out)[row * 256 + 128 + c] = v;
    __nv_bfloat162 h0, h1;
    h0.x = __float2bfloat16_rn(v.x); h0.y = __float2bfloat16_rn(v.y);
    h1.x = __float2bfloat16_rn(v.z); h1.y = __float2bfloat16_rn(v.w);
    ((__nv_bfloat162*)dst)[i * 2]     = h0;
    ((__nv_bfloat162*)dst)[i * 2 + 1] = h1;
}

// ---------------------------------------------------------------------------
// memory gather+convert: compact row j <- memory[idx[j]]; zeros for j >= nc.
// Produces mem_c [1024,512] bf16 and memT_c [512,1024] bf16 per batch.
// ---------------------------------------------------------------------------
__global__ __launch_bounds__(256)
void conv_memory_kernel(const float* __restrict__ src,
                        bf16* __restrict__ mem_c, bf16* __restrict__ memT)
{
    __shared__ float t[32][33];
    const int bx = blockIdx.x * 32;   // over d (512)
    const int by = blockIdx.y * 32;   // over compact j (1024)
    const int bz = blockIdx.z;
    const size_t bo = (size_t)bz * SK * ATTD;
    const int nc = g_nc[bz];
    const int* idx = g_idx + (size_t)bz * SK;
    src += bo; mem_c += bo; memT += bo;

    #pragma unroll
    for (int i = threadIdx.y; i < 32; i += 8) {
        const int j = by + i;
        float v = 0.f;
        if (j < nc)
            v = src[(size_t)idx[j] * ATTD + bx + threadIdx.x];
        t[i][threadIdx.x] = v;
        mem_c[(size_t)j * ATTD + bx + threadIdx.x] = __float2bfloat16_rn(v);
    }
    __syncthreads();
    #pragma unroll
    for (int i = threadIdx.y; i < 32; i += 8)
        memT[(size_t)(bx + i) * SK + by + threadIdx.x] =
            __float2bfloat16_rn(t[threadIdx.x][i]);
}

// ---------------------------------------------------------------------------
// W [512,512] fp32 -> W^T bf16 ; z selects Wi / Wm
// ---------------------------------------------------------------------------
__global__ __launch_bounds__(256)
void convW_kernel(const float* __restrict__ Wi, const float* __restrict__ Wm,
                  bf16* __restrict__ wiT, bf16* __restrict__ wmT)
{
    __shared__ float t[32][33];
    const float* src = blockIdx.z ? Wm : Wi;
    bf16* dstT = blockIdx.z ? wmT : wiT;
    const int bx = blockIdx.x * 32;
    const int by = blockIdx.y * 32;
    #pragma unroll
    for (int i = threadIdx.y; i < 32; i += 8)
        t[i][threadIdx.x] = src[(size_t)(by + i) * ATTD + bx + threadIdx.x];
    __syncthreads();
    #pragma unroll
    for (int i = threadIdx.y; i < 32; i += 8)
        dstT[(size_t)(bx + i) * ATTD + by + threadIdx.x] =
            __float2bfloat16_rn(t[threadIdx.x][i]);
}

// ---------------------------------------------------------------------------
extern "C" void kernel_launch(void* const* d_in, const int* in_sizes, int n_in,
                              void* d_out, int out_size)
{
    const float* inputs = (const float*)d_in[0];
    const float* memory = (const float*)d_in[1];
    const int*   mask   = (const int*)d_in[2];
    const float* Wi     = (const float*)d_in[3];
    const float* Wm     = (const float*)d_in[4];
    float* out = (float*)d_out;

    cudaFuncSetAttribute(gemm_mma_kernel<512, 0>,  cudaFuncAttributeMaxDynamicSharedMemorySize, DSMEM);
    cudaFuncSetAttribute(gemm_mma_kernel<512, 2>,  cudaFuncAttributeMaxDynamicSharedMemorySize, DSMEM);
    cudaFuncSetAttribute(gemm_mma_kernel<1024, 3>, cudaFuncAttributeMaxDynamicSharedMemorySize, DSMEM);

    bf16 *in_b, *mem_c, *wiT, *wmT, *x_b, *m_b, *memT, *p_b;
    float* rinv;
    cudaGetSymbolAddress((void**)&in_b, g_in_b);
    cudaGetSymbolAddress((void**)&mem_c, g_mem_c);
    cudaGetSymbolAddress((void**)&wiT, g_wiT);
    cudaGetSymbolAddress((void**)&wmT, g_wmT);
    cudaGetSymbolAddress((void**)&x_b, g_x);
    cudaGetSymbolAddress((void**)&m_b, g_m);
    cudaGetSymbolAddress((void**)&memT, g_memT);
    cudaGetSymbolAddress((void**)&p_b, g_p);
    cudaGetSymbolAddress((void**)&rinv, g_rinv);

    // 0) mask prefix scan -> idx / nc / nc_pad
    mask_scan_kernel<<<BATCH, 1024>>>(mask);

    // 1) conversions (inputs+concat fused; memory gathered+transposed; both W)
    conv_inputs_kernel<<<16384, 256>>>(inputs, in_b, out);
    conv_memory_kernel<<<dim3(16, 32, 32), dim3(32, 8)>>>(memory, mem_c, memT);
    convW_kernel<<<dim3(16, 16, 2), dim3(32, 8)>>>(Wi, Wm, wiT, wmT);

    // 2) both projections in ONE launch (z=0: x path, z=1: compact m path)
    gemm_mma_kernel<512, 0><<<dim3(4, 256, 2), 256, DSMEM>>>(
        in_b, 0, wiT, 0, nullptr, nullptr, x_b, mem_c, wmT, m_b);

    // 3) logits over compact keys -> masked exp -> g_p
    gemm_mma_kernel<512, 2><<<dim3(8, 8, 32), 256, DSMEM>>>(
        x_b, (size_t)SQ * ATTD, m_b, (size_t)SK * ATTD, nullptr,
        nullptr, p_b, nullptr, nullptr, nullptr);

    // 4) per-row reciprocal sums (compact bounds)
    rowsum_kernel<<<BATCH * SQ / 8, 256>>>();

    // 5) context: (P_c @ mem_c) * rinv -> out[:, :512]; runtime K = nc_pad[b]
    gemm_mma_kernel<1024, 3><<<dim3(4, 8, 32), 256, DSMEM>>>(
        p_b, (size_t)SQ * SK, memT, (size_t)ATTD * SK, rinv,
        out, nullptr, nullptr, nullptr, nullptr);
}

// round 9
// speedup vs baseline: 9.3715x; 1.0512x over previous
#include <cuda_runtime.h>
#include <cuda_bf16.h>
#include <cstdint>

#define BATCH 32
#define SQ 1024
#define SK 1024
#define ATTD 512
#define SCALE 0.044194173824159216f   // 1/sqrt(512)

typedef __nv_bfloat16 bf16;

// ---------------------------------------------------------------------------
// Scratch (static device globals — no runtime allocation)
// ---------------------------------------------------------------------------
__device__ bf16 g_in_b [(size_t)BATCH * SQ * ATTD];    // inputs bf16
__device__ bf16 g_mem_c[(size_t)BATCH * SK * ATTD];    // gathered (unmasked) memory bf16
__device__ bf16 g_wiT  [(size_t)ATTD * ATTD];          // Wi^T bf16
__device__ bf16 g_wmT  [(size_t)ATTD * ATTD];          // Wm^T bf16
__device__ bf16 g_x    [(size_t)BATCH * SQ * ATTD];    // relu(in@Wi)*scale
__device__ bf16 g_m    [(size_t)BATCH * SK * ATTD];    // relu(mem_c@Wm) (compact rows)
__device__ bf16 g_memT [(size_t)BATCH * ATTD * SK];    // gathered memory^T per batch
__device__ bf16 g_p    [(size_t)BATCH * SQ * SK];      // exp(logits) compact, pad->0
__device__ float g_psum[(size_t)BATCH * SQ * 8];       // per-(row, n128-tile) exp sums
__device__ int  g_idx  [(size_t)BATCH * SK];           // compact -> original key index
__device__ int  g_nc   [BATCH];                        // # unmasked keys
__device__ int  g_ncp  [BATCH];                        // nc padded to 128
__device__ int  g_ncp64[BATCH];                        // nc padded to 64

// ---------------------------------------------------------------------------
// PTX helpers
// ---------------------------------------------------------------------------
__device__ __forceinline__ uint32_t s2u(const void* p) {
    return (uint32_t)__cvta_generic_to_shared(p);
}
__device__ __forceinline__ void cp_async16(uint32_t dst, const void* src) {
    asm volatile("cp.async.cg.shared.global [%0], [%1], 16;" :: "r"(dst), "l"(src));
}
#define CP_COMMIT() asm volatile("cp.async.commit_group;" ::: "memory")
#define CP_WAIT1()  asm volatile("cp.async.wait_group 1;" ::: "memory")

__device__ __forceinline__ void ldsm_x4(uint32_t* r, uint32_t addr) {
    asm volatile("ldmatrix.sync.aligned.m8n8.x4.shared.b16 {%0,%1,%2,%3}, [%4];"
                 : "=r"(r[0]), "=r"(r[1]), "=r"(r[2]), "=r"(r[3]) : "r"(addr));
}
__device__ __forceinline__ void mma16816(float* d, const uint32_t* a, const uint32_t* b) {
    asm volatile(
        "mma.sync.aligned.m16n8k16.row.col.f32.bf16.bf16.f32 "
        "{%0,%1,%2,%3}, {%4,%5,%6,%7}, {%8,%9}, {%0,%1,%2,%3};"
        : "+f"(d[0]), "+f"(d[1]), "+f"(d[2]), "+f"(d[3])
        : "r"(a[0]), "r"(a[1]), "r"(a[2]), "r"(a[3]), "r"(b[0]), "r"(b[1]));
}

// ---------------------------------------------------------------------------
// mask prefix scan: per batch builds idx list (ascending), nc, pads
// ---------------------------------------------------------------------------
__global__ __launch_bounds__(1024)
void mask_scan_kernel(const int* __restrict__ mask)
{
    __shared__ int s[1024];
    const int b = blockIdx.x;
    const int t = threadIdx.x;
    const int v = mask[(size_t)b * SK + t] != 0;
    s[t] = v;
    __syncthreads();
    #pragma unroll
    for (int off = 1; off < 1024; off <<= 1) {
        int x = 0;
        if (t >= off) x = s[t - off];
        __syncthreads();
        if (t >= off) s[t] += x;
        __syncthreads();
    }
    if (v) g_idx[(size_t)b * SK + s[t] - 1] = t;
    if (t == 1023) {
        g_nc[b]    = s[1023];
        g_ncp[b]   = (s[1023] + 127) & ~127;
        g_ncp64[b] = (s[1023] + 63) & ~63;
    }
}

// ---------------------------------------------------------------------------
// bf16 mma.sync GEMM: tile 128x128x64, 8 warps (4m x 2n), 3-stage cp.async.
// EPI: 0 proj (z=0: relu*SCALE -> obf ; z=1: relu -> obf2, compact-M early exit)
//      2 logits (compact-N early exit; exp, zero pad -> obf; row partial sums -> g_psum)
//      3 context (runtime K = ncp64[b]; rinv from g_psum; fp32 -> outf)
// ---------------------------------------------------------------------------
#define STAGES 3
#define STAGE_BYTES 32768
#define DSMEM (STAGES * STAGE_BYTES + 1024)

__device__ __forceinline__ uint32_t sw_off(int row, int kb) {
    return (uint32_t)(row * 128 + ((kb ^ (row & 7)) << 4));
}

template<int K, int EPI>
__global__ void __launch_bounds__(256, 2)
gemm_mma_kernel(const bf16* __restrict__ A, size_t aBS,
                const bf16* __restrict__ B, size_t bBS,
                float* __restrict__ outf,
                bf16* __restrict__ obf,
                const bf16* __restrict__ A2, const bf16* __restrict__ B2,
                bf16* __restrict__ obf2)
{
    extern __shared__ char dsm_raw[];
    __shared__ float s_rinv[128];
    __shared__ float s_part[2][128];

    const int tid  = threadIdx.x;
    const int wid  = tid >> 5;
    const int lane = tid & 31;
    const int n0 = blockIdx.x * 128;
    const int m0 = blockIdx.y * 128;
    const int b  = blockIdx.z;

    // ---- compaction-driven early exits / runtime K ----
    int nc = 0;
    if (EPI == 0) {
        if (b == 1 && (m0 & (SK - 1)) >= g_ncp[m0 >> 10]) return;
    } else if (EPI == 2) {
        if (n0 >= g_ncp[b]) return;
        nc = g_nc[b];
    }
    int NC = K / 64;
    if (EPI == 3) NC = g_ncp64[b] >> 6;

    const uint32_t smem0 = (s2u(dsm_raw) + 1023u) & ~1023u;

    if (EPI == 3 && tid < 128) {
        const int nt8 = g_ncp[b] >> 7;
        const float* ps = g_psum + ((size_t)b * SQ + m0 + tid) * 8;
        float s = 0.f;
        for (int t = 0; t < nt8; t++) s += ps[t];
        s_rinv[tid] = 1.0f / s;
    }

    const bf16* Abase = A;
    const bf16* Bbase = B;
    bf16* obase = obf;
    if (EPI == 0 && b == 1) { Abase = A2; Bbase = B2; obase = obf2; }

    const bf16* Ag = Abase + (size_t)b * aBS + (size_t)m0 * K;
    const bf16* Bg = Bbase + (size_t)b * bBS + (size_t)n0 * K;

    uint32_t dsw[4];
    size_t   sof[4];
    #pragma unroll
    for (int u = 0; u < 4; u++) {
        int i = tid + u * 256;
        int r = i >> 3, kb = i & 7;
        dsw[u] = sw_off(r, kb);
        sof[u] = (size_t)r * K + kb * 8;
    }

    #define ISSUE_STAGE(kt_) do {                                        \
        uint32_t sb_ = smem0 + ((kt_) % STAGES) * STAGE_BYTES;           \
        size_t ko_ = (size_t)(kt_) * 64;                                 \
        _Pragma("unroll")                                                \
        for (int u = 0; u < 4; u++) {                                    \
            cp_async16(sb_ + dsw[u],         Ag + sof[u] + ko_);         \
            cp_async16(sb_ + dsw[u] + 16384, Bg + sof[u] + ko_);         \
        }                                                                \
    } while (0)

    ISSUE_STAGE(0); CP_COMMIT();
    ISSUE_STAGE(1); CP_COMMIT();      // prefetch addresses are always in-bounds

    const int wm = (wid & 3) * 32;
    const int wn = (wid >> 2) * 64;

    float acc[2][8][4];
    #pragma unroll
    for (int i = 0; i < 2; i++)
        #pragma unroll
        for (int j = 0; j < 8; j++)
            #pragma unroll
            for (int q = 0; q < 4; q++) acc[i][j][q] = 0.f;

    const int a_row = wm + (lane & 15);
    const int a_kb  = lane >> 4;
    const int b_row = wn + (lane & 7) + ((lane >> 4) & 1) * 8;
    const int b_kb  = (lane >> 3) & 1;

    for (int kt = 0; kt < NC; kt++) {
        CP_WAIT1();
        __syncthreads();

        const uint32_t sb = smem0 + (kt % STAGES) * STAGE_BYTES;

        #pragma unroll
        for (int ks = 0; ks < 4; ks++) {
            uint32_t af[2][4];
            #pragma unroll
            for (int mt = 0; mt < 2; mt++)
                ldsm_x4(af[mt], sb + sw_off(a_row + mt * 16, a_kb + ks * 2));
            #pragma unroll
            for (int g = 0; g < 4; g++) {
                uint32_t bfog[4];
                ldsm_x4(bfog, sb + 16384 + sw_off(b_row + g * 16, b_kb + ks * 2));
                #pragma unroll
                for (int mt = 0; mt < 2; mt++) {
                    mma16816(acc[mt][2 * g + 0], af[mt], bfog + 0);
                    mma16816(acc[mt][2 * g + 1], af[mt], bfog + 2);
                }
            }
        }

        if (kt + 2 < NC) ISSUE_STAGE(kt + 2);
        CP_COMMIT();
    }
    #undef ISSUE_STAGE

    // ------------------------- epilogue -------------------------
    const int er = lane >> 2;
    const int ec = (lane & 3) * 2;
    const float scl = (EPI == 0 && b == 0) ? SCALE : 1.0f;

    float sA[2] = {0.f, 0.f}, sB[2] = {0.f, 0.f};   // EPI2 row partial sums

    #pragma unroll
    for (int mt = 0; mt < 2; mt++) {
        #pragma unroll
        for (int nt = 0; nt < 8; nt++) {
            const int rA = m0 + wm + mt * 16 + er;
            const int rB = rA + 8;
            const int cl = wn + nt * 8 + ec;
            float v0 = acc[mt][nt][0], v1 = acc[mt][nt][1];
            float v2 = acc[mt][nt][2], v3 = acc[mt][nt][3];

            if (EPI == 0) {
                v0 = fmaxf(v0, 0.f) * scl; v1 = fmaxf(v1, 0.f) * scl;
                v2 = fmaxf(v2, 0.f) * scl; v3 = fmaxf(v3, 0.f) * scl;
                __nv_bfloat162 h0, h1;
                h0.x = __float2bfloat16_rn(v0); h0.y = __float2bfloat16_rn(v1);
                h1.x = __float2bfloat16_rn(v2); h1.y = __float2bfloat16_rn(v3);
                *(__nv_bfloat162*)(obase + (size_t)rA * ATTD + n0 + cl) = h0;
                *(__nv_bfloat162*)(obase + (size_t)rB * ATTD + n0 + cl) = h1;
            } else if (EPI == 2) {
                const bool c0 = (n0 + cl)     < nc;
                const bool c1 = (n0 + cl + 1) < nc;
                float e0 = c0 ? __expf(v0) : 0.f;
                float e1 = c1 ? __expf(v1) : 0.f;
                float e2 = c0 ? __expf(v2) : 0.f;
                float e3 = c1 ? __expf(v3) : 0.f;
                sA[mt] += e0 + e1;
                sB[mt] += e2 + e3;
                __nv_bfloat162 h0, h1;
                h0.x = __float2bfloat16_rn(e0); h0.y = __float2bfloat16_rn(e1);
                h1.x = __float2bfloat16_rn(e2); h1.y = __float2bfloat16_rn(e3);
                size_t base = (size_t)b * SQ * SK;
                *(__nv_bfloat162*)(obf + base + (size_t)rA * SK + n0 + cl) = h0;
                *(__nv_bfloat162*)(obf + base + (size_t)rB * SK + n0 + cl) = h1;
            } else {  // EPI 3: context * rinv -> out[:, :512], row stride 1024
                const float iA = s_rinv[wm + mt * 16 + er];
                const float iB = s_rinv[wm + mt * 16 + er + 8];
                float2 w0, w1;
                w0.x = v0 * iA; w0.y = v1 * iA;
                w1.x = v2 * iB; w1.y = v3 * iB;
                *(float2*)(outf + ((size_t)b * SQ + rA) * 1024 + n0 + cl) = w0;
                *(float2*)(outf + ((size_t)b * SQ + rB) * 1024 + n0 + cl) = w1;
            }
        }
    }

    if (EPI == 2) {
        // reduce row sums: quad lanes (ec) -> smem across the 2 n-warps -> g_psum
        #pragma unroll
        for (int mt = 0; mt < 2; mt++) {
            float a = sA[mt], bb = sB[mt];
            a  += __shfl_xor_sync(0xffffffffu, a, 1);
            a  += __shfl_xor_sync(0xffffffffu, a, 2);
            bb += __shfl_xor_sync(0xffffffffu, bb, 1);
            bb += __shfl_xor_sync(0xffffffffu, bb, 2);
            if ((lane & 3) == 0) {
                s_part[wid >> 2][wm + mt * 16 + er]     = a;
                s_part[wid >> 2][wm + mt * 16 + er + 8] = bb;
            }
        }
        __syncthreads();
        if (tid < 128) {
            float tot = s_part[0][tid] + s_part[1][tid];
            g_psum[((size_t)b * SQ + m0 + tid) * 8 + (n0 >> 7)] = tot;
        }
    }
}

// ---------------------------------------------------------------------------
// merged conversions, dispatched by block range:
//  [0, 16384)      : inputs fp32 -> bf16 + concat copy to out[:, 512:]
//  [16384, 32768)  : memory gather+convert -> mem_c and memT (zero pad)
//  [32768, 33280)  : W -> W^T bf16 (z selects Wi/Wm)
// ---------------------------------------------------------------------------
__global__ __launch_bounds__(256)
void conv_all_kernel(const float* __restrict__ inputs,
                     const float* __restrict__ memory,
                     const float* __restrict__ Wi, const float* __restrict__ Wm,
                     bf16* __restrict__ in_b, float* __restrict__ out,
                     bf16* __restrict__ mem_c, bf16* __restrict__ memT,
                     bf16* __restrict__ wiT, bf16* __restrict__ wmT)
{
    __shared__ float t[32][33];
    const int id  = blockIdx.x;
    const int tid = threadIdx.x;

    if (id < 16384) {
        const size_t i = (size_t)id * 256 + tid;    // float4 index
        const size_t row = i >> 7;
        const size_t c = i & 127;
        float4 v = ((const float4*)inputs)[i];
        ((float4*)out)[row * 256 + 128 + c] = v;    // concat half (exact fp32)
        __nv_bfloat162 h0, h1;
        h0.x = __float2bfloat16_rn(v.x); h0.y = __float2bfloat16_rn(v.y);
        h1.x = __float2bfloat16_rn(v.z); h1.y = __float2bfloat16_rn(v.w);
        ((__nv_bfloat162*)in_b)[i * 2]     = h0;
        ((__nv_bfloat162*)in_b)[i * 2 + 1] = h1;
    } else if (id < 32768) {
        const int jid = id - 16384;
        const int bx = (jid & 15) * 32;            // over d (512)
        const int by = ((jid >> 4) & 31) * 32;     // over compact j (1024)
        const int bz = jid >> 9;                   // batch
        const int tx = tid & 31, ty = tid >> 5;
        const size_t bo = (size_t)bz * SK * ATTD;
        const int nc = g_nc[bz];
        const int* idx = g_idx + (size_t)bz * SK;
        const float* src = memory + bo;
        bf16* mc = mem_c + bo;
        bf16* mt = memT + bo;

        #pragma unroll
        for (int i = ty; i < 32; i += 8) {
            const int j = by + i;
            float v = 0.f;
            if (j < nc)
                v = src[(size_t)idx[j] * ATTD + bx + tx];
            t[i][tx] = v;
            mc[(size_t)j * ATTD + bx + tx] = __float2bfloat16_rn(v);
        }
        __syncthreads();
        #pragma unroll
        for (int i = ty; i < 32; i += 8)
            mt[(size_t)(bx + i) * SK + by + tx] = __float2bfloat16_rn(t[tx][i]);
    } else {
        const int jid = id - 32768;
        const int bx = (jid & 15) * 32;
        const int by = ((jid >> 4) & 15) * 32;
        const int z  = jid >> 8;
        const int tx = tid & 31, ty = tid >> 5;
        const float* src = z ? Wm : Wi;
        bf16* dstT = z ? wmT : wiT;

        #pragma unroll
        for (int i = ty; i < 32; i += 8)
            t[i][tx] = src[(size_t)(by + i) * ATTD + bx + tx];
        __syncthreads();
        #pragma unroll
        for (int i = ty; i < 32; i += 8)
            dstT[(size_t)(bx + i) * ATTD + by + tx] =
                __float2bfloat16_rn(t[tx][i]);
    }
}

// ---------------------------------------------------------------------------
extern "C" void kernel_launch(void* const* d_in, const int* in_sizes, int n_in,
                              void* d_out, int out_size)
{
    const float* inputs = (const float*)d_in[0];
    const float* memory = (const float*)d_in[1];
    const int*   mask   = (const int*)d_in[2];
    const float* Wi     = (const float*)d_in[3];
    const float* Wm     = (const float*)d_in[4];
    float* out = (float*)d_out;

    cudaFuncSetAttribute(gemm_mma_kernel<512, 0>,  cudaFuncAttributeMaxDynamicSharedMemorySize, DSMEM);
    cudaFuncSetAttribute(gemm_mma_kernel<512, 2>,  cudaFuncAttributeMaxDynamicSharedMemorySize, DSMEM);
    cudaFuncSetAttribute(gemm_mma_kernel<1024, 3>, cudaFuncAttributeMaxDynamicSharedMemorySize, DSMEM);

    bf16 *in_b, *mem_c, *wiT, *wmT, *x_b, *m_b, *memT, *p_b;
    cudaGetSymbolAddress((void**)&in_b, g_in_b);
    cudaGetSymbolAddress((void**)&mem_c, g_mem_c);
    cudaGetSymbolAddress((void**)&wiT, g_wiT);
    cudaGetSymbolAddress((void**)&wmT, g_wmT);
    cudaGetSymbolAddress((void**)&x_b, g_x);
    cudaGetSymbolAddress((void**)&m_b, g_m);
    cudaGetSymbolAddress((void**)&memT, g_memT);
    cudaGetSymbolAddress((void**)&p_b, g_p);

    // 0) mask prefix scan -> idx / nc / pads
    mask_scan_kernel<<<BATCH, 1024>>>(mask);

    // 1) all conversions in ONE launch (inputs+concat | memory gather+T | W^T)
    conv_all_kernel<<<33280, 256>>>(inputs, memory, Wi, Wm,
                                    in_b, out, mem_c, memT, wiT, wmT);

    // 2) both projections in ONE launch (z=0: x path, z=1: compact m path)
    gemm_mma_kernel<512, 0><<<dim3(4, 256, 2), 256, DSMEM>>>(
        in_b, 0, wiT, 0, nullptr, x_b, mem_c, wmT, m_b);

    // 3) logits over compact keys -> exp -> g_p ; row partial sums -> g_psum
    gemm_mma_kernel<512, 2><<<dim3(8, 8, 32), 256, DSMEM>>>(
        x_b, (size_t)SQ * ATTD, m_b, (size_t)SK * ATTD,
        nullptr, p_b, nullptr, nullptr, nullptr);

    // 4) context: (P_c @ mem_c) * rinv -> out[:, :512]; runtime K = ncp64[b]
    gemm_mma_kernel<1024, 3><<<dim3(4, 8, 32), 256, DSMEM>>>(
        p_b, (size_t)SQ * SK, memT, (size_t)ATTD * SK,
        out, nullptr, nullptr, nullptr, nullptr);
}

// round 10
// speedup vs baseline: 9.4489x; 1.0083x over previous
#include <cuda_runtime.h>
#include <cuda_bf16.h>
#include <cstdint>

#define BATCH 32
#define SQ 1024
#define SK 1024
#define ATTD 512
#define SCALE 0.044194173824159216f   // 1/sqrt(512)

typedef __nv_bfloat16 bf16;

// ---------------------------------------------------------------------------
// Scratch (static device globals — no runtime allocation)
// ---------------------------------------------------------------------------
__device__ bf16 g_in_b [(size_t)BATCH * SQ * ATTD];    // inputs bf16
__device__ bf16 g_mem_c[(size_t)BATCH * SK * ATTD];    // gathered (unmasked) memory bf16
__device__ bf16 g_wiT  [(size_t)ATTD * ATTD];          // Wi^T bf16
__device__ bf16 g_wmT  [(size_t)ATTD * ATTD];          // Wm^T bf16
__device__ bf16 g_x    [(size_t)BATCH * SQ * ATTD];    // relu(in@Wi)*scale
__device__ bf16 g_m    [(size_t)BATCH * SK * ATTD];    // relu(mem_c@Wm) (compact rows)
__device__ bf16 g_memT [(size_t)BATCH * ATTD * SK];    // gathered memory^T per batch
__device__ bf16 g_p    [(size_t)BATCH * SQ * SK];      // exp(logits) compact, pad->0
__device__ float g_psum[(size_t)BATCH * SQ * 8];       // per-(row, n128-tile) exp sums
__device__ int  g_idx  [(size_t)BATCH * SK];           // compact -> original key index
__device__ int  g_nc   [BATCH];                        // # unmasked keys
__device__ int  g_ncp  [BATCH];                        // nc padded to 128
__device__ int  g_ncp64[BATCH];                        // nc padded to 64

// ---------------------------------------------------------------------------
// PTX helpers
// ---------------------------------------------------------------------------
__device__ __forceinline__ uint32_t s2u(const void* p) {
    return (uint32_t)__cvta_generic_to_shared(p);
}
__device__ __forceinline__ void cp_async16(uint32_t dst, const void* src) {
    asm volatile("cp.async.cg.shared.global [%0], [%1], 16;" :: "r"(dst), "l"(src));
}
#define CP_COMMIT() asm volatile("cp.async.commit_group;" ::: "memory")
#define CP_WAIT1()  asm volatile("cp.async.wait_group 1;" ::: "memory")

__device__ __forceinline__ void ldsm_x4(uint32_t* r, uint32_t addr) {
    asm volatile("ldmatrix.sync.aligned.m8n8.x4.shared.b16 {%0,%1,%2,%3}, [%4];"
                 : "=r"(r[0]), "=r"(r[1]), "=r"(r[2]), "=r"(r[3]) : "r"(addr));
}
__device__ __forceinline__ void mma16816(float* d, const uint32_t* a, const uint32_t* b) {
    asm volatile(
        "mma.sync.aligned.m16n8k16.row.col.f32.bf16.bf16.f32 "
        "{%0,%1,%2,%3}, {%4,%5,%6,%7}, {%8,%9}, {%0,%1,%2,%3};"
        : "+f"(d[0]), "+f"(d[1]), "+f"(d[2]), "+f"(d[3])
        : "r"(a[0]), "r"(a[1]), "r"(a[2]), "r"(a[3]), "r"(b[0]), "r"(b[1]));
}

// ---------------------------------------------------------------------------
// mask prefix scan: per batch builds idx list (ascending), nc, pads
// ---------------------------------------------------------------------------
__global__ __launch_bounds__(1024)
void mask_scan_kernel(const int* __restrict__ mask)
{
    __shared__ int s[1024];
    const int b = blockIdx.x;
    const int t = threadIdx.x;
    const int v = mask[(size_t)b * SK + t] != 0;
    s[t] = v;
    __syncthreads();
    #pragma unroll
    for (int off = 1; off < 1024; off <<= 1) {
        int x = 0;
        if (t >= off) x = s[t - off];
        __syncthreads();
        if (t >= off) s[t] += x;
        __syncthreads();
    }
    if (v) g_idx[(size_t)b * SK + s[t] - 1] = t;
    if (t == 1023) {
        g_nc[b]    = s[1023];
        g_ncp[b]   = (s[1023] + 127) & ~127;
        g_ncp64[b] = (s[1023] + 63) & ~63;
    }
}

// ---------------------------------------------------------------------------
// bf16 mma.sync GEMM: CTA tile 128x128x64, FOUR warps (2x2 grid of 64x64 warp
// tiles -> 32 flops per smem byte, the SM balance point), 3-stage cp.async.
// EPI: 0 proj (z=0: relu*SCALE -> obf ; z=1: relu -> obf2, compact-M early exit)
//      2 logits (compact-N early exit; exp, zero pad -> obf; row sums -> g_psum)
//      3 context (runtime K = ncp64[b]; rinv from g_psum; fp32 -> outf)
// ---------------------------------------------------------------------------
#define STAGES 3
#define STAGE_BYTES 32768
#define DSMEM (STAGES * STAGE_BYTES + 1024)

__device__ __forceinline__ uint32_t sw_off(int row, int kb) {
    return (uint32_t)(row * 128 + ((kb ^ (row & 7)) << 4));
}

template<int K, int EPI>
__global__ void __launch_bounds__(128, 2)
gemm_mma_kernel(const bf16* __restrict__ A, size_t aBS,
                const bf16* __restrict__ B, size_t bBS,
                float* __restrict__ outf,
                bf16* __restrict__ obf,
                const bf16* __restrict__ A2, const bf16* __restrict__ B2,
                bf16* __restrict__ obf2)
{
    extern __shared__ char dsm_raw[];
    __shared__ float s_rinv[128];
    __shared__ float s_part[2][128];

    const int tid  = threadIdx.x;
    const int wid  = tid >> 5;
    const int lane = tid & 31;
    const int n0 = blockIdx.x * 128;
    const int m0 = blockIdx.y * 128;
    const int b  = blockIdx.z;

    // ---- compaction-driven early exits / runtime K ----
    int nc = 0;
    if (EPI == 0) {
        if (b == 1 && (m0 & (SK - 1)) >= g_ncp[m0 >> 10]) return;
    } else if (EPI == 2) {
        if (n0 >= g_ncp[b]) return;
        nc = g_nc[b];
    }
    int NC = K / 64;
    if (EPI == 3) NC = g_ncp64[b] >> 6;

    const uint32_t smem0 = (s2u(dsm_raw) + 1023u) & ~1023u;

    if (EPI == 3) {
        const int nt8 = g_ncp[b] >> 7;
        const float* ps = g_psum + ((size_t)b * SQ + m0 + tid) * 8;
        float s = 0.f;
        for (int t = 0; t < nt8; t++) s += ps[t];
        s_rinv[tid] = 1.0f / s;
    }

    const bf16* Abase = A;
    const bf16* Bbase = B;
    bf16* obase = obf;
    if (EPI == 0 && b == 1) { Abase = A2; Bbase = B2; obase = obf2; }

    const bf16* Ag = Abase + (size_t)b * aBS + (size_t)m0 * K;
    const bf16* Bg = Bbase + (size_t)b * bBS + (size_t)n0 * K;

    // loader: 128 threads x 8 slots cover 128 rows x 64 bf16 per array
    uint32_t dsw[8];
    uint32_t sof[8];   // element offsets (fit 32-bit)
    #pragma unroll
    for (int u = 0; u < 8; u++) {
        int i = tid + u * 128;
        int r = i >> 3, kb = i & 7;
        dsw[u] = sw_off(r, kb);
        sof[u] = (uint32_t)(r * K + kb * 8);
    }

    #define ISSUE_STAGE(kt_) do {                                        \
        uint32_t sb_ = smem0 + ((kt_) % STAGES) * STAGE_BYTES;           \
        uint32_t ko_ = (uint32_t)(kt_) * 64;                             \
        _Pragma("unroll")                                                \
        for (int u = 0; u < 8; u++) {                                    \
            cp_async16(sb_ + dsw[u],         Ag + sof[u] + ko_);         \
            cp_async16(sb_ + dsw[u] + 16384, Bg + sof[u] + ko_);         \
        }                                                                \
    } while (0)

    ISSUE_STAGE(0); CP_COMMIT();
    ISSUE_STAGE(1); CP_COMMIT();      // prefetch addresses are always in-bounds

    const int wm = (wid & 1) * 64;    // 2x2 warp grid, 64x64 tiles
    const int wn = (wid >> 1) * 64;

    float acc[4][8][4];
    #pragma unroll
    for (int i = 0; i < 4; i++)
        #pragma unroll
        for (int j = 0; j < 8; j++)
            #pragma unroll
            for (int q = 0; q < 4; q++) acc[i][j][q] = 0.f;

    const int a_row = wm + (lane & 15);
    const int a_kb  = lane >> 4;
    const int b_row = wn + (lane & 7) + ((lane >> 4) & 1) * 8;
    const int b_kb  = (lane >> 3) & 1;

    for (int kt = 0; kt < NC; kt++) {
        CP_WAIT1();
        __syncthreads();

        const uint32_t sb = smem0 + (kt % STAGES) * STAGE_BYTES;

        #pragma unroll
        for (int ks = 0; ks < 4; ks++) {
            uint32_t af[4][4];
            #pragma unroll
            for (int mt = 0; mt < 4; mt++)
                ldsm_x4(af[mt], sb + sw_off(a_row + mt * 16, a_kb + ks * 2));
            #pragma unroll
            for (int g = 0; g < 4; g++) {
                uint32_t bfog[4];
                ldsm_x4(bfog, sb + 16384 + sw_off(b_row + g * 16, b_kb + ks * 2));
                #pragma unroll
                for (int mt = 0; mt < 4; mt++) {
                    mma16816(acc[mt][2 * g + 0], af[mt], bfog + 0);
                    mma16816(acc[mt][2 * g + 1], af[mt], bfog + 2);
                }
            }
        }

        if (kt + 2 < NC) ISSUE_STAGE(kt + 2);
        CP_COMMIT();
    }
    #undef ISSUE_STAGE

    // ------------------------- epilogue -------------------------
    const int er = lane >> 2;
    const int ec = (lane & 3) * 2;
    const float scl = (EPI == 0 && b == 0) ? SCALE : 1.0f;

    float sA[4] = {0.f, 0.f, 0.f, 0.f}, sB[4] = {0.f, 0.f, 0.f, 0.f};

    #pragma unroll
    for (int mt = 0; mt < 4; mt++) {
        #pragma unroll
        for (int nt = 0; nt < 8; nt++) {
            const int rA = m0 + wm + mt * 16 + er;
            const int rB = rA + 8;
            const int cl = wn + nt * 8 + ec;
            float v0 = acc[mt][nt][0], v1 = acc[mt][nt][1];
            float v2 = acc[mt][nt][2], v3 = acc[mt][nt][3];

            if (EPI == 0) {
                v0 = fmaxf(v0, 0.f) * scl; v1 = fmaxf(v1, 0.f) * scl;
                v2 = fmaxf(v2, 0.f) * scl; v3 = fmaxf(v3, 0.f) * scl;
                __nv_bfloat162 h0, h1;
                h0.x = __float2bfloat16_rn(v0); h0.y = __float2bfloat16_rn(v1);
                h1.x = __float2bfloat16_rn(v2); h1.y = __float2bfloat16_rn(v3);
                *(__nv_bfloat162*)(obase + (size_t)rA * ATTD + n0 + cl) = h0;
                *(__nv_bfloat162*)(obase + (size_t)rB * ATTD + n0 + cl) = h1;
            } else if (EPI == 2) {
                const bool c0 = (n0 + cl)     < nc;
                const bool c1 = (n0 + cl + 1) < nc;
                float e0 = c0 ? __expf(v0) : 0.f;
                float e1 = c1 ? __expf(v1) : 0.f;
                float e2 = c0 ? __expf(v2) : 0.f;
                float e3 = c1 ? __expf(v3) : 0.f;
                sA[mt] += e0 + e1;
                sB[mt] += e2 + e3;
                __nv_bfloat162 h0, h1;
                h0.x = __float2bfloat16_rn(e0); h0.y = __float2bfloat16_rn(e1);
                h1.x = __float2bfloat16_rn(e2); h1.y = __float2bfloat16_rn(e3);
                size_t base = (size_t)b * SQ * SK;
                *(__nv_bfloat162*)(obf + base + (size_t)rA * SK + n0 + cl) = h0;
                *(__nv_bfloat162*)(obf + base + (size_t)rB * SK + n0 + cl) = h1;
            } else {  // EPI 3: context * rinv -> out[:, :512], row stride 1024
                const float iA = s_rinv[wm + mt * 16 + er];
                const float iB = s_rinv[wm + mt * 16 + er + 8];
                float2 w0, w1;
                w0.x = v0 * iA; w0.y = v1 * iA;
                w1.x = v2 * iB; w1.y = v3 * iB;
                *(float2*)(outf + ((size_t)b * SQ + rA) * 1024 + n0 + cl) = w0;
                *(float2*)(outf + ((size_t)b * SQ + rB) * 1024 + n0 + cl) = w1;
            }
        }
    }

    if (EPI == 2) {
        // reduce row sums: quad lanes -> smem per n-warp-group -> g_psum
        #pragma unroll
        for (int mt = 0; mt < 4; mt++) {
            float a = sA[mt], bb = sB[mt];
            a  += __shfl_xor_sync(0xffffffffu, a, 1);
            a  += __shfl_xor_sync(0xffffffffu, a, 2);
            bb += __shfl_xor_sync(0xffffffffu, bb, 1);
            bb += __shfl_xor_sync(0xffffffffu, bb, 2);
            if ((lane & 3) == 0) {
                s_part[wid >> 1][wm + mt * 16 + er]     = a;
                s_part[wid >> 1][wm + mt * 16 + er + 8] = bb;
            }
        }
        __syncthreads();
        float tot = s_part[0][tid] + s_part[1][tid];
        g_psum[((size_t)b * SQ + m0 + tid) * 8 + (n0 >> 7)] = tot;
    }
}

// ---------------------------------------------------------------------------
// merged conversions, dispatched by block range:
//  [0, 16384)      : inputs fp32 -> bf16 + concat copy to out[:, 512:]
//  [16384, 32768)  : memory gather+convert -> mem_c and memT (zero pad)
//  [32768, 33280)  : W -> W^T bf16 (z selects Wi/Wm)
// ---------------------------------------------------------------------------
__global__ __launch_bounds__(256)
void conv_all_kernel(const float* __restrict__ inputs,
                     const float* __restrict__ memory,
                     const float* __restrict__ Wi, const float* __restrict__ Wm,
                     bf16* __restrict__ in_b, float* __restrict__ out,
                     bf16* __restrict__ mem_c, bf16* __restrict__ memT,
                     bf16* __restrict__ wiT, bf16* __restrict__ wmT)
{
    __shared__ float t[32][33];
    const int id  = blockIdx.x;
    const int tid = threadIdx.x;

    if (id < 16384) {
        const size_t i = (size_t)id * 256 + tid;    // float4 index
        const size_t row = i >> 7;
        const size_t c = i & 127;
        float4 v = ((const float4*)inputs)[i];
        ((float4*)out)[row * 256 + 128 + c] = v;    // concat half (exact fp32)
        __nv_bfloat162 h0, h1;
        h0.x = __float2bfloat16_rn(v.x); h0.y = __float2bfloat16_rn(v.y);
        h1.x = __float2bfloat16_rn(v.z); h1.y = __float2bfloat16_rn(v.w);
        ((__nv_bfloat162*)in_b)[i * 2]     = h0;
        ((__nv_bfloat162*)in_b)[i * 2 + 1] = h1;
    } else if (id < 32768) {
        const int jid = id - 16384;
        const int bx = (jid & 15) * 32;            // over d (512)
        const int by = ((jid >> 4) & 31) * 32;     // over compact j (1024)
        const int bz = jid >> 9;                   // batch
        const int tx = tid & 31, ty = tid >> 5;
        const size_t bo = (size_t)bz * SK * ATTD;
        const int nc = g_nc[bz];
        const int* idx = g_idx + (size_t)bz * SK;
        const float* src = memory + bo;
        bf16* mc = mem_c + bo;
        bf16* mt = memT + bo;

        #pragma unroll
        for (int i = ty; i < 32; i += 8) {
            const int j = by + i;
            float v = 0.f;
            if (j < nc)
                v = src[(size_t)idx[j] * ATTD + bx + tx];
            t[i][tx] = v;
            mc[(size_t)j * ATTD + bx + tx] = __float2bfloat16_rn(v);
        }
        __syncthreads();
        #pragma unroll
        for (int i = ty; i < 32; i += 8)
            mt[(size_t)(bx + i) * SK + by + tx] = __float2bfloat16_rn(t[tx][i]);
    } else {
        const int jid = id - 32768;
        const int bx = (jid & 15) * 32;
        const int by = ((jid >> 4) & 15) * 32;
        const int z  = jid >> 8;
        const int tx = tid & 31, ty = tid >> 5;
        const float* src = z ? Wm : Wi;
        bf16* dstT = z ? wmT : wiT;

        #pragma unroll
        for (int i = ty; i < 32; i += 8)
            t[i][tx] = src[(size_t)(by + i) * ATTD + bx + tx];
        __syncthreads();
        #pragma unroll
        for (int i = ty; i < 32; i += 8)
            dstT[(size_t)(bx + i) * ATTD + by + tx] =
                __float2bfloat16_rn(t[tx][i]);
    }
}

// ---------------------------------------------------------------------------
extern "C" void kernel_launch(void* const* d_in, const int* in_sizes, int n_in,
                              void* d_out, int out_size)
{
    const float* inputs = (const float*)d_in[0];
    const float* memory = (const float*)d_in[1];
    const int*   mask   = (const int*)d_in[2];
    const float* Wi     = (const float*)d_in[3];
    const float* Wm     = (const float*)d_in[4];
    float* out = (float*)d_out;

    cudaFuncSetAttribute(gemm_mma_kernel<512, 0>,  cudaFuncAttributeMaxDynamicSharedMemorySize, DSMEM);
    cudaFuncSetAttribute(gemm_mma_kernel<512, 2>,  cudaFuncAttributeMaxDynamicSharedMemorySize, DSMEM);
    cudaFuncSetAttribute(gemm_mma_kernel<1024, 3>, cudaFuncAttributeMaxDynamicSharedMemorySize, DSMEM);

    bf16 *in_b, *mem_c, *wiT, *wmT, *x_b, *m_b, *memT, *p_b;
    cudaGetSymbolAddress((void**)&in_b, g_in_b);
    cudaGetSymbolAddress((void**)&mem_c, g_mem_c);
    cudaGetSymbolAddress((void**)&wiT, g_wiT);
    cudaGetSymbolAddress((void**)&wmT, g_wmT);
    cudaGetSymbolAddress((void**)&x_b, g_x);
    cudaGetSymbolAddress((void**)&m_b, g_m);
    cudaGetSymbolAddress((void**)&memT, g_memT);
    cudaGetSymbolAddress((void**)&p_b, g_p);

    // 0) mask prefix scan -> idx / nc / pads
    mask_scan_kernel<<<BATCH, 1024>>>(mask);

    // 1) all conversions in ONE launch (inputs+concat | memory gather+T | W^T)
    conv_all_kernel<<<33280, 256>>>(inputs, memory, Wi, Wm,
                                    in_b, out, mem_c, memT, wiT, wmT);

    // 2) both projections in ONE launch (z=0: x path, z=1: compact m path)
    gemm_mma_kernel<512, 0><<<dim3(4, 256, 2), 128, DSMEM>>>(
        in_b, 0, wiT, 0, nullptr, x_b, mem_c, wmT, m_b);

    // 3) logits over compact keys -> exp -> g_p ; row partial sums -> g_psum
    gemm_mma_kernel<512, 2><<<dim3(8, 8, 32), 128, DSMEM>>>(
        x_b, (size_t)SQ * ATTD, m_b, (size_t)SK * ATTD,
        nullptr, p_b, nullptr, nullptr, nullptr);

    // 4) context: (P_c @ mem_c) * rinv -> out[:, :512]; runtime K = ncp64[b]
    gemm_mma_kernel<1024, 3><<<dim3(4, 8, 32), 128, DSMEM>>>(
        p_b, (size_t)SQ * SK, memT, (size_t)ATTD * SK,
        out, nullptr, nullptr, nullptr, nullptr);
}